// round 8
// baseline (speedup 1.0000x reference)
#include <cuda_runtime.h>
#include <cuda_bf16.h>
#include <cstdint>
#include <cstddef>

// ---------------- problem constants ----------------
#define NSAMP   4096
#define IDIM    512
#define HDIM    128
#define LSTRIDE (HDIM + HDIM*HDIM)       // 16512 rows of W per layer
#define NLAYER  3

// ---------------- tiling ----------------
#define NB      32                        // samples per CTA (GEMM N)
#define CHUNKS  129                       // 128 weight chunks + 1 x-chunk
#define SPC     8                         // 64-k slabs per chunk (K=512)
#define PSEUDO  3                         // bias-fold pseudo slabs (K=192, zero-padded)
#define SPL     (CHUNKS*SPC + PSEUDO)     // 1035 slabs per layer
#define NSLAB   (NLAYER*SPL)              // 3105 slabs total
static_assert(NSLAB % 3 == 0, "wrap-prefetch slot map needs NSLAB % 3 == 0");

// Hybrid mode: F (fp32 CUDA cores) for 5 of 8 slabs, T (bf16 HMMA) for 3 of 8.
#define IS_F(ls) (((ls) & 7) < 5)

#define WSLAB   32768                     // 32KB slab image (both modes)
#define ZSLAB   8192                      // 8KB Z image (both modes)

#define XP      520                       // xs pitch (floats)
#define HP      132                       // hs pitch (floats)

#define OFF_W   0                         // 3 * 32768
#define OFF_Z   (3*WSLAB)                 // 2 * 8192 (also layer-end 16KB grid)
#define OFF_X   (OFF_Z + 2*ZSLAB)
#define OFF_H   (OFF_X + NB*XP*4)
#define SMEM_ALLOC (OFF_H + NB*HP*4 + 1024)

#define THREADS 512

#define SW128(x) ((x) ^ (((x) >> 3) & 0x70))

// ---------------- ptx helpers ----------------
__device__ __forceinline__ uint32_t smem_u32(const void* p) {
    uint32_t a;
    asm("{ .reg .u64 t; cvta.to.shared.u64 t, %1; cvt.u32.u64 %0, t; }" : "=r"(a) : "l"(p));
    return a;
}
__device__ __forceinline__ void cp16(uint32_t s, const void* g) {
    asm volatile("cp.async.cg.shared.global [%0], [%1], 16;" :: "r"(s), "l"(g));
}
#define CP_COMMIT() asm volatile("cp.async.commit_group;" ::: "memory")
#define CP_WAIT1()  asm volatile("cp.async.wait_group 1;" ::: "memory")
#define CP_WAIT0()  asm volatile("cp.async.wait_group 0;" ::: "memory")

__device__ __forceinline__ void ldsm4(uint32_t& r0, uint32_t& r1, uint32_t& r2,
                                      uint32_t& r3, uint32_t addr) {
    asm volatile("ldmatrix.sync.aligned.m8n8.x4.shared.b16 {%0,%1,%2,%3}, [%4];"
                 : "=r"(r0), "=r"(r1), "=r"(r2), "=r"(r3) : "r"(addr));
}
__device__ __forceinline__ void mma_bf16(float* d, const uint32_t* a,
                                         uint32_t b0, uint32_t b1) {
    asm volatile(
        "mma.sync.aligned.m16n8k16.row.col.f32.bf16.bf16.f32 "
        "{%0,%1,%2,%3}, {%4,%5,%6,%7}, {%8,%9}, {%0,%1,%2,%3};"
        : "+f"(d[0]), "+f"(d[1]), "+f"(d[2]), "+f"(d[3])
        : "r"(a[0]), "r"(a[1]), "r"(a[2]), "r"(a[3]), "r"(b0), "r"(b1));
}
__device__ __forceinline__ void fma2(unsigned long long &c, unsigned long long a,
                                     unsigned long long b) {
    asm("fma.rn.f32x2 %0, %1, %2, %0;" : "+l"(c) : "l"(a), "l"(b));
}
__device__ __forceinline__ void lds_v2u64(unsigned long long& a, unsigned long long& b,
                                          uint32_t addr) {
    asm volatile("ld.shared.v2.u64 {%0,%1}, [%2];" : "=l"(a), "=l"(b) : "r"(addr));
}
__device__ __forceinline__ void sts_v4f32(uint32_t addr, float x, float y, float z, float w) {
    asm volatile("st.shared.v4.f32 [%0], {%1,%2,%3,%4};"
                 :: "r"(addr), "f"(x), "f"(y), "f"(z), "f"(w) : "memory");
}
__device__ __forceinline__ void split2(float v0, float v1, unsigned& hi, unsigned& lo) {
    __nv_bfloat16 h0 = __float2bfloat16(v0), h1 = __float2bfloat16(v1);
    float r0 = v0 - __bfloat162float(h0);
    float r1 = v1 - __bfloat162float(h1);
    __nv_bfloat16 l0 = __float2bfloat16(r0), l1 = __float2bfloat16(r1);
    hi = (unsigned)__bfloat16_as_ushort(h0) | ((unsigned)__bfloat16_as_ushort(h1) << 16);
    lo = (unsigned)__bfloat16_as_ushort(l0) | ((unsigned)__bfloat16_as_ushort(l1) << 16);
}

// W pack: per-slab 32KB images in stream order. Format per mode:
//  T: bf16 hi (16K SW128) + bf16 lo (16K SW128)
//  F: fp32 [128 rows x 64 k], 16B granules stored at g^((g>>3)&1)
__device__ __align__(16) unsigned char g_wpack[(size_t)NSLAB * WSLAB];

// ---------------- prep kernel ----------------
__global__ void prep_kernel(const float* __restrict__ W, const float* __restrict__ b) {
    const int s    = blockIdx.x;
    const int l    = s / SPL;
    const int sl   = s - l * SPL;
    const int base = l * LSTRIDE;
    unsigned char* dst = g_wpack + (size_t)s * WSLAB;

    if (IS_F(sl)) {
        // fp32 granule-folded layout: 2048 tasks (row r, granule g of 4 floats)
        for (int task = threadIdx.x; task < 2048; task += blockDim.x) {
            const int r = task >> 4, g = task & 15;
            float v[4];
            if (sl < CHUNKS * SPC) {
                const int c = sl >> 3, j = sl & 7;
                const int row = base + (c < HDIM ? HDIM + c * HDIM + r : r);
                const float* src = W + (size_t)row * IDIM + j * 64 + g * 4;
                #pragma unroll
                for (int e = 0; e < 4; ++e) v[e] = src[e];
            } else {
                const int j = sl - CHUNKS * SPC;
                #pragma unroll
                for (int e = 0; e < 4; ++e) {
                    const int kg = j * 64 + g * 4 + e;
                    v[e] = (kg < HDIM) ? b[base + HDIM + kg * HDIM + r]
                                       : (kg == HDIM ? b[base + r] : 0.f);
                }
            }
            const int gp = g ^ ((g >> 3) & 1);
            *(float4*)(dst + r * 256 + gp * 16) = make_float4(v[0], v[1], v[2], v[3]);
        }
    } else {
        for (int task = threadIdx.x; task < 1024; task += blockDim.x) {
            const int r = task >> 3, kb = task & 7;
            float v[8];
            if (sl < CHUNKS * SPC) {
                const int c = sl >> 3, j = sl & 7;
                const int row = base + (c < HDIM ? HDIM + c * HDIM + r : r);
                const float* src = W + (size_t)row * IDIM + j * 64 + kb * 8;
                #pragma unroll
                for (int e = 0; e < 8; ++e) v[e] = src[e];
            } else {
                const int j = sl - CHUNKS * SPC;
                #pragma unroll
                for (int e = 0; e < 8; ++e) {
                    const int kg = j * 64 + kb * 8 + e;
                    v[e] = (kg < HDIM) ? b[base + HDIM + kg * HDIM + r]
                                       : (kg == HDIM ? b[base + r] : 0.f);
                }
            }
            unsigned hi[4], lo[4];
            #pragma unroll
            for (int e = 0; e < 4; ++e) split2(v[2*e], v[2*e+1], hi[e], lo[e]);
            const unsigned off = SW128(r * 128 + kb * 16);
            *(uint4*)(dst + off)         = make_uint4(hi[0], hi[1], hi[2], hi[3]);
            *(uint4*)(dst + 16384 + off) = make_uint4(lo[0], lo[1], lo[2], lo[3]);
        }
    }
}

// ---------------- main fused hybrid kernel ----------------
__global__ void __launch_bounds__(THREADS, 1)
inet_hyb_kernel(const float* __restrict__ gx_int, const float* __restrict__ gx,
                float* __restrict__ gout)
{
    extern __shared__ __align__(16) unsigned char smraw[];
    const uint32_t sb0 = smem_u32(smraw);
    const uint32_t sb  = (sb0 + 1023) & ~1023u;
    unsigned char* sm  = smraw + (sb - sb0);
    float* xs = (float*)(sm + OFF_X);
    float* hs = (float*)(sm + OFF_H);

    const int tid = threadIdx.x;
    const int wid = tid >> 5, lid = tid & 31;
    const int n0  = blockIdx.x * NB;

    // T-mode (HMMA) lane geometry
    const int w7  = wid & 7;                // q rows 16*w7..+16
    const int kg2 = (wid >> 3) * 2;         // k-steps kg2, kg2+1
    const int g   = lid >> 3, lr = lid & 7;
    const int aoff = (16*w7 + (g & 1)*8 + lr) * 128 + (g >> 1) * 16;
    const int boff = ((g >> 1)*8 + lr) * 128 + (g & 1) * 16;

    // F-mode (fp32) lane geometry: warp owns q rows 8*wid..+8
    const int ngF = lid >> 2;               // n = ngF + 8*nn
    const int kgF = lid & 3;                // k = 16*kgF .. +16

    // Stage int_x tile (fp32) and initial h = x.
    for (int i = tid; i < NB * (IDIM/4); i += THREADS) {
        int n = i >> 7, k4 = i & 127;
        cp16(sb + OFF_X + (n*XP + k4*4)*4, gx_int + (size_t)(n0+n)*IDIM + k4*4);
    }
    for (int i = tid; i < NB * (HDIM/4); i += THREADS) {
        int n = i >> 5, q4 = i & 31;
        cp16(sb + OFF_H + (n*HP + q4*4)*4, gx + (size_t)(n0+n)*HDIM + q4*4);
    }
    CP_COMMIT(); CP_WAIT0();
    __syncthreads();

    // Prologue: W slabs 0,1 into ring slots 0,1.
    #pragma unroll 1
    for (int p = 0; p < 2; ++p) {
        const unsigned char* src = g_wpack + (size_t)p * WSLAB + tid * 64;
        uint32_t d = sb + OFF_W + p * WSLAB + tid * 64;
        #pragma unroll
        for (int v = 0; v < 4; ++v) cp16(d + v*16, src + v*16);
        CP_COMMIT();
    }

    // Z generator (mode-dependent format).
    auto zgen = [&](int ls, int slot) {
        unsigned char* zp = sm + OFF_Z + slot * ZSLAB;
        if (IS_F(ls)) {
            const int zn = tid >> 4, zg = tid & 15;     // row, granule of 4
            float v[4];
            if (ls < CHUNKS * SPC) {
                const int c = ls >> 3, j = ls & 7;
                const float m = (c < HDIM) ? hs[zn*HP + c] : 1.0f;
                const float4 xv = *(const float4*)&xs[zn*XP + j*64 + zg*4];
                v[0] = m*xv.x; v[1] = m*xv.y; v[2] = m*xv.z; v[3] = m*xv.w;
            } else {
                const int j = ls - CHUNKS * SPC;
                #pragma unroll
                for (int e = 0; e < 4; ++e) {
                    const int kg = j*64 + zg*4 + e;
                    v[e] = (kg < HDIM) ? hs[zn*HP + kg] : (kg == HDIM ? 1.f : 0.f);
                }
            }
            const int gp = (zg ^ ((zg >> 3) & 1)) ^ (zn & 7);
            sts_v4f32(smem_u32(zp) + zn*256 + gp*16, v[0], v[1], v[2], v[3]);
        } else {
            const int zn = tid >> 4, zkb = tid & 15;    // row, 4-elem k block
            const unsigned zoff = SW128(zn * 128 + zkb * 8);
            float v[4];
            if (ls < CHUNKS * SPC) {
                const int c = ls >> 3, j = ls & 7;
                const float m = (c < HDIM) ? hs[zn*HP + c] : 1.0f;
                const float4 xv = *(const float4*)&xs[zn*XP + j*64 + zkb*4];
                v[0] = m*xv.x; v[1] = m*xv.y; v[2] = m*xv.z; v[3] = m*xv.w;
            } else {
                const int j = ls - CHUNKS * SPC;
                #pragma unroll
                for (int e = 0; e < 4; ++e) {
                    const int kg = j*64 + zkb*4 + e;
                    v[e] = (kg < HDIM) ? hs[zn*HP + kg] : (kg == HDIM ? 1.f : 0.f);
                }
            }
            unsigned hi[2], lo[2];
            split2(v[0], v[1], hi[0], lo[0]);
            split2(v[2], v[3], hi[1], lo[1]);
            *(uint2*)(zp + zoff)        = make_uint2(hi[0], hi[1]);
            *(uint2*)(zp + 4096 + zoff) = make_uint2(lo[0], lo[1]);
        }
    };

    int s = 0;
    for (int layer = 0; layer < NLAYER; ++layer) {
        float hacc[4][4];                       // T partials (fragment layout)
        #pragma unroll
        for (int t = 0; t < 4; ++t)
            #pragma unroll
            for (int i = 0; i < 4; ++i) hacc[t][i] = 0.f;
        unsigned long long facc[32];            // F partials: [qq][nn] float2(k-even,k-odd)
        #pragma unroll
        for (int i = 0; i < 32; ++i) facc[i] = 0ull;

        zgen(0, 0);

        for (int ls = 0; ls < SPL; ++ls, ++s) {
            CP_WAIT1();
            __syncthreads();

            // Prefetch W slab s+2 (streams under compute).
            {
                const int pf = (s + 2) % NSLAB;
                const unsigned char* src = g_wpack + (size_t)pf * WSLAB + tid * 64;
                uint32_t d = sb + OFF_W + (pf % 3) * WSLAB + tid * 64;
                #pragma unroll
                for (int v = 0; v < 4; ++v) cp16(d + v*16, src + v*16);
                CP_COMMIT();
            }
            if (ls + 1 < SPL) zgen(ls + 1, (ls + 1) & 1);

            const uint32_t wb = sb + OFF_W + (s % 3) * WSLAB;
            const uint32_t zb = sb + OFF_Z + (ls & 1) * ZSLAB;

            if (IS_F(ls)) {
                // fp32 path: thread tile 8q x 4n x 16k via packed f32x2 FMAs.
                #pragma unroll
                for (int j = 0; j < 4; ++j) {
                    const int gg = 4*kgF + j;
                    const int gw = gg ^ ((gg >> 3) & 1);
                    const int gz = gw ^ ngF;
                    unsigned long long zu[4][2];
                    #pragma unroll
                    for (int nn = 0; nn < 4; ++nn)
                        lds_v2u64(zu[nn][0], zu[nn][1], zb + (ngF + 8*nn)*256 + gz*16);
                    #pragma unroll
                    for (int qq = 0; qq < 8; ++qq) {
                        unsigned long long wu0, wu1;
                        lds_v2u64(wu0, wu1, wb + (8*wid + qq)*256 + gw*16);
                        #pragma unroll
                        for (int nn = 0; nn < 4; ++nn) {
                            fma2(facc[qq*4+nn], wu0, zu[nn][0]);
                            fma2(facc[qq*4+nn], wu1, zu[nn][1]);
                        }
                    }
                }
            } else {
                // HMMA path: this warp-group's half of K (k-steps kg2, kg2+1).
                #pragma unroll
                for (int kx = 0; kx < 2; ++kx) {
                    const int kk = kg2 + kx;
                    uint32_t ah[4], al[4], bh[8], bl[8];
                    ldsm4(ah[0], ah[1], ah[2], ah[3], wb + SW128(aoff + kk*32));
                    ldsm4(al[0], al[1], al[2], al[3], wb + 16384 + SW128(aoff + kk*32));
                    ldsm4(bh[0], bh[1], bh[2], bh[3], zb + SW128(boff + kk*32));
                    ldsm4(bh[4], bh[5], bh[6], bh[7], zb + SW128(boff + 2048 + kk*32));
                    ldsm4(bl[0], bl[1], bl[2], bl[3], zb + 4096 + SW128(boff + kk*32));
                    ldsm4(bl[4], bl[5], bl[6], bl[7], zb + 4096 + SW128(boff + 2048 + kk*32));
                    #pragma unroll
                    for (int t = 0; t < 4; ++t) {
                        mma_bf16(hacc[t], ah, bh[2*t], bh[2*t+1]);
                        mma_bf16(hacc[t], al, bh[2*t], bh[2*t+1]);
                        mma_bf16(hacc[t], ah, bl[2*t], bl[2*t+1]);
                    }
                }
            }
        }

        // ---- layer epilogue: merge T + F partials via 16KB smem grid ----
        __syncthreads();
        float* grid = (float*)(sm + OFF_Z);     // [128][32]
        const int qb = 16*w7 + (lid >> 2);
        const int nbT = 2 * (lid & 3);
        if (wid < 8) {                           // T group A writes
            #pragma unroll
            for (int t = 0; t < 4; ++t) {
                const int n = 8*t + nbT;
                grid[(qb    )*32 + n    ] = hacc[t][0];
                grid[(qb    )*32 + n + 1] = hacc[t][1];
                grid[(qb + 8)*32 + n    ] = hacc[t][2];
                grid[(qb + 8)*32 + n + 1] = hacc[t][3];
            }
        }
        __syncthreads();
        if (wid >= 8) {                          // T group B adds
            #pragma unroll
            for (int t = 0; t < 4; ++t) {
                const int n = 8*t + nbT;
                grid[(qb    )*32 + n    ] += hacc[t][0];
                grid[(qb    )*32 + n + 1] += hacc[t][1];
                grid[(qb + 8)*32 + n    ] += hacc[t][2];
                grid[(qb + 8)*32 + n + 1] += hacc[t][3];
            }
        }
        __syncthreads();
        #pragma unroll
        for (int p = 0; p < 4; ++p) {            // F k-groups add, serialized
            if (kgF == p) {
                #pragma unroll
                for (int qq = 0; qq < 8; ++qq)
                    #pragma unroll
                    for (int nn = 0; nn < 4; ++nn) {
                        union { unsigned long long u; float2 f; } cv;
                        cv.u = facc[qq*4+nn];
                        grid[(8*wid + qq)*32 + (ngF + 8*nn)] += cv.f.x + cv.f.y;
                    }
            }
            __syncthreads();
        }
        // read back: 8 cells per thread
        {
            const int base = tid * 8;
            if (layer < NLAYER - 1) {
                #pragma unroll
                for (int e = 0; e < 8; ++e) {
                    const int q = (base + e) >> 5, n = (base + e) & 31;
                    hs[n*HP + q] = fmaxf(grid[(base + e)], 0.f) * ((q*32+n)==(base+e) ? 1.f : 1.f);
                }
            } else {
                #pragma unroll
                for (int e = 0; e < 8; ++e) {
                    const int q = (base + e) >> 5, n = (base + e) & 31;
                    gout[(size_t)(n0 + n)*HDIM + q] = grid[base + e];
                }
            }
        }
        __syncthreads();                         // grid/hs settled before next zgen
    }
}

extern "C" void kernel_launch(void* const* d_in, const int* in_sizes, int n_in,
                              void* d_out, int out_size)
{
    const float *int_x = nullptr, *x = nullptr, *W = nullptr, *b = nullptr;
    for (int i = 0; i < n_in; ++i) {
        const int sz = in_sizes[i];
        if      (sz == NSAMP*IDIM)          int_x = (const float*)d_in[i];
        else if (sz == NSAMP*HDIM)          x     = (const float*)d_in[i];
        else if (sz == NLAYER*LSTRIDE*IDIM) W     = (const float*)d_in[i];
        else if (sz == NLAYER*LSTRIDE)      b     = (const float*)d_in[i];
    }

    prep_kernel<<<NSLAB, 256>>>(W, b);

    cudaFuncSetAttribute(inet_hyb_kernel, cudaFuncAttributeMaxDynamicSharedMemorySize,
                         SMEM_ALLOC);
    inet_hyb_kernel<<<NSAMP/NB, THREADS, SMEM_ALLOC>>>(int_x, x, (float*)d_out);
}

// round 9
// speedup vs baseline: 2.6219x; 2.6219x over previous
#include <cuda_runtime.h>
#include <cuda_bf16.h>
#include <cstdint>
#include <cstddef>

// ---------------- problem constants ----------------
#define NSAMP   4096
#define IDIM    512
#define HDIM    128
#define LSTRIDE (HDIM + HDIM*HDIM)       // 16512 rows of W per layer
#define NLAYER  3

// ---------------- tiling ----------------
#define NB      32                        // samples per CTA (GEMM N)
#define CHUNKS  129                       // 128 weight chunks + 1 x-chunk
#define SPC     8                         // 64-k slabs per chunk (K=512)
#define PSEUDO  3                         // bias-fold pseudo slabs (K=192, zero-padded)
#define SPL     (CHUNKS*SPC + PSEUDO)     // 1035 slabs per layer
#define NSLAB   (NLAYER*SPL)              // 3105 slabs total

#define WSLAB   32768                     // [128 x 64] bf16, hi(16K) + lo(16K), SW128
#define ZSLAB   8192                      // [32 x 64]  bf16, hi(4K)  + lo(4K),  SW128

#define XP      520                       // xs pitch (floats)
#define HP      132                       // hs pitch (floats)

#define OFF_W   0                         // 3 * 32768
#define OFF_Z   (3*WSLAB)                 // 2 * 8192 (also layer-end scratch)
#define OFF_X   (OFF_Z + 2*ZSLAB)
#define OFF_H   (OFF_X + NB*XP*4)
#define OFF_MB  (OFF_H + NB*HP*4)         // 3 mbarriers (8B each)
#define SMEM_ALLOC (OFF_MB + 64 + 1024)

#define THREADS 512                       // 16 warps: k-split into 2 groups of 8

#define SW128(x) ((x) ^ (((x) >> 3) & 0x70))

// ---------------- ptx helpers ----------------
__device__ __forceinline__ uint32_t smem_u32(const void* p) {
    uint32_t a;
    asm("{ .reg .u64 t; cvta.to.shared.u64 t, %1; cvt.u32.u64 %0, t; }" : "=r"(a) : "l"(p));
    return a;
}
__device__ __forceinline__ void cp16(uint32_t s, const void* g) {
    asm volatile("cp.async.cg.shared.global [%0], [%1], 16;" :: "r"(s), "l"(g));
}
#define CP_COMMIT() asm volatile("cp.async.commit_group;" ::: "memory")
#define CP_WAIT0()  asm volatile("cp.async.wait_group 0;" ::: "memory")

// Bulk async copy (single UBLKCP; completion via mbarrier complete_tx).
__device__ __forceinline__ void bulk_cp(uint32_t dst, const void* src,
                                        uint32_t bytes, uint32_t mbar) {
    asm volatile(
        "cp.async.bulk.shared::cta.global.mbarrier::complete_tx::bytes [%0], [%1], %2, [%3];"
        :: "r"(dst), "l"(src), "r"(bytes), "r"(mbar) : "memory");
}
__device__ __forceinline__ void mbar_init(uint32_t a, uint32_t cnt) {
    asm volatile("mbarrier.init.shared.b64 [%0], %1;" :: "r"(a), "r"(cnt) : "memory");
}
__device__ __forceinline__ void mbar_expect_tx(uint32_t a, uint32_t bytes) {
    asm volatile("mbarrier.arrive.expect_tx.shared.b64 _, [%0], %1;"
                 :: "r"(a), "r"(bytes) : "memory");
}
__device__ __forceinline__ void mbar_wait(uint32_t a, uint32_t parity) {
    uint32_t done;
    asm volatile(
        "{\n\t.reg .pred p;\n\t"
        "mbarrier.try_wait.parity.acquire.cta.shared::cta.b64 p, [%1], %2;\n\t"
        "selp.b32 %0, 1, 0, p;\n\t}" : "=r"(done) : "r"(a), "r"(parity) : "memory");
    if (!done) {
        asm volatile(
            "{\n\t.reg .pred P1;\n\t"
            "W_%=:\n\t"
            "mbarrier.try_wait.parity.acquire.cta.shared::cta.b64 P1, [%0], %1, 0x989680;\n\t"
            "@P1 bra.uni D_%=;\n\t"
            "bra.uni W_%=;\n\t"
            "D_%=:\n\t}" :: "r"(a), "r"(parity) : "memory");
    }
}

__device__ __forceinline__ void ldsm4(uint32_t& r0, uint32_t& r1, uint32_t& r2,
                                      uint32_t& r3, uint32_t addr) {
    asm volatile("ldmatrix.sync.aligned.m8n8.x4.shared.b16 {%0,%1,%2,%3}, [%4];"
                 : "=r"(r0), "=r"(r1), "=r"(r2), "=r"(r3) : "r"(addr));
}
__device__ __forceinline__ void mma_bf16(float* d, const uint32_t* a,
                                         uint32_t b0, uint32_t b1) {
    asm volatile(
        "mma.sync.aligned.m16n8k16.row.col.f32.bf16.bf16.f32 "
        "{%0,%1,%2,%3}, {%4,%5,%6,%7}, {%8,%9}, {%0,%1,%2,%3};"
        : "+f"(d[0]), "+f"(d[1]), "+f"(d[2]), "+f"(d[3])
        : "r"(a[0]), "r"(a[1]), "r"(a[2]), "r"(a[3]), "r"(b0), "r"(b1));
}
__device__ __forceinline__ void split2(float v0, float v1, unsigned& hi, unsigned& lo) {
    __nv_bfloat16 h0 = __float2bfloat16(v0), h1 = __float2bfloat16(v1);
    float r0 = v0 - __bfloat162float(h0);
    float r1 = v1 - __bfloat162float(h1);
    __nv_bfloat16 l0 = __float2bfloat16(r0), l1 = __float2bfloat16(r1);
    hi = (unsigned)__bfloat16_as_ushort(h0) | ((unsigned)__bfloat16_as_ushort(h1) << 16);
    lo = (unsigned)__bfloat16_as_ushort(l0) | ((unsigned)__bfloat16_as_ushort(l1) << 16);
}

// W pack: per-slab 32KB images (hi 16KB + lo 16KB), pre-swizzled, in stream order.
__device__ __align__(128) unsigned char g_wpack[(size_t)NSLAB * WSLAB];

// ---------------- prep: split W/b to bf16 hi/lo slab images ----------------
__global__ void prep_kernel(const float* __restrict__ W, const float* __restrict__ b) {
    const int s    = blockIdx.x;
    const int l    = s / SPL;
    const int sl   = s - l * SPL;
    const int base = l * LSTRIDE;
    unsigned char* dst = g_wpack + (size_t)s * WSLAB;

    for (int task = threadIdx.x; task < 1024; task += blockDim.x) {
        const int r = task >> 3, kb = task & 7;         // row 0..127, 8-elem k block
        float v[8];
        if (sl < CHUNKS * SPC) {
            const int c = sl >> 3, j = sl & 7;
            const int row = base + (c < HDIM ? HDIM + c * HDIM + r : r);
            const float* src = W + (size_t)row * IDIM + j * 64 + kb * 8;
            #pragma unroll
            for (int e = 0; e < 8; ++e) v[e] = src[e];
        } else {                                        // bias-fold pseudo slab
            const int j = sl - CHUNKS * SPC;
            #pragma unroll
            for (int e = 0; e < 8; ++e) {
                const int kg = j * 64 + kb * 8 + e;
                v[e] = (kg < HDIM) ? b[base + HDIM + kg * HDIM + r]
                                   : (kg == HDIM ? b[base + r] : 0.f);
            }
        }
        unsigned hi[4], lo[4];
        #pragma unroll
        for (int e = 0; e < 4; ++e) split2(v[2*e], v[2*e+1], hi[e], lo[e]);
        const unsigned off = SW128(r * 128 + kb * 16);
        *(uint4*)(dst + off)         = make_uint4(hi[0], hi[1], hi[2], hi[3]);
        *(uint4*)(dst + 16384 + off) = make_uint4(lo[0], lo[1], lo[2], lo[3]);
    }
}

// ---------------- main fused kernel ----------------
__global__ void __launch_bounds__(THREADS, 1)
inet_mma_kernel(const float* __restrict__ gx_int, const float* __restrict__ gx,
                float* __restrict__ gout)
{
    extern __shared__ __align__(16) unsigned char smraw[];
    const uint32_t sb0 = smem_u32(smraw);
    const uint32_t sb  = (sb0 + 1023) & ~1023u;        // 1024-align for SW128
    unsigned char* sm  = smraw + (sb - sb0);
    float* xs = (float*)(sm + OFF_X);
    float* hs = (float*)(sm + OFF_H);

    const int tid = threadIdx.x;
    const int wid = tid >> 5, lid = tid & 31;
    const int w7  = wid & 7;                // q-block owner (rows 16*w7..16*w7+15)
    const int kg2 = (wid >> 3) * 2;         // this warp's k-steps: kg2, kg2+1
    const int n0  = blockIdx.x * NB;

    // Per-lane ldmatrix offset bases (bytes, pre-swizzle).
    const int g  = lid >> 3, lr = lid & 7;
    const int aoff = (16*w7 + (g & 1)*8 + lr) * 128 + (g >> 1) * 16;   // A: W rows
    const int boff = ((g >> 1)*8 + lr) * 128 + (g & 1) * 16;           // B: Z rows

    // mbarriers for the 3-slot W ring.
    if (tid == 0)
        for (int k = 0; k < 3; ++k) mbar_init(sb + OFF_MB + k * 8, 1);

    // Stage int_x tile (fp32) and initial h = x.
    for (int i = tid; i < NB * (IDIM/4); i += THREADS) {
        int n = i >> 7, k4 = i & 127;
        cp16(sb + OFF_X + (n*XP + k4*4)*4, gx_int + (size_t)(n0+n)*IDIM + k4*4);
    }
    for (int i = tid; i < NB * (HDIM/4); i += THREADS) {
        int n = i >> 5, q4 = i & 31;
        cp16(sb + OFF_H + (n*HP + q4*4)*4, gx + (size_t)(n0+n)*HDIM + q4*4);
    }
    CP_COMMIT(); CP_WAIT0();
    __syncthreads();                        // also orders mbar_init before use

    // Prologue: W slabs 0,1 -> ring slots 0,1 via single bulk copies.
    if (tid == 0) {
        #pragma unroll
        for (int p = 0; p < 2; ++p) {
            mbar_expect_tx(sb + OFF_MB + p * 8, WSLAB);
            bulk_cp(sb + OFF_W + p * WSLAB, g_wpack + (size_t)p * WSLAB,
                    WSLAB, sb + OFF_MB + p * 8);
        }
    }

    // Z generator: slab ls of current layer -> Z slot (hi/lo bf16, swizzled).
    const int zn = tid >> 4, zkb = tid & 15;            // row, 4-elem k block
    auto zgen = [&](int ls, int slot) {
        unsigned char* zp = sm + OFF_Z + slot * ZSLAB;
        const unsigned zoff = SW128(zn * 128 + zkb * 8);
        float v[4];
        if (ls < CHUNKS * SPC) {
            const int c = ls >> 3, j = ls & 7;
            const float m = (c < HDIM) ? hs[zn*HP + c] : 1.0f;
            const float4 xv = *(const float4*)&xs[zn*XP + j*64 + zkb*4];
            v[0] = m*xv.x; v[1] = m*xv.y; v[2] = m*xv.z; v[3] = m*xv.w;
        } else {
            const int j = ls - CHUNKS * SPC;
            #pragma unroll
            for (int e = 0; e < 4; ++e) {
                const int kg = j*64 + zkb*4 + e;
                v[e] = (kg < HDIM) ? hs[zn*HP + kg] : (kg == HDIM ? 1.f : 0.f);
            }
        }
        unsigned hi[2], lo[2];
        split2(v[0], v[1], hi[0], lo[0]);
        split2(v[2], v[3], hi[1], lo[1]);
        *(uint2*)(zp + zoff)        = make_uint2(hi[0], hi[1]);
        *(uint2*)(zp + 4096 + zoff) = make_uint2(lo[0], lo[1]);
    };

    int s = 0;
    for (int layer = 0; layer < NLAYER; ++layer) {
        float acc[4][4];
        #pragma unroll
        for (int t = 0; t < 4; ++t)
            #pragma unroll
            for (int i = 0; i < 4; ++i) acc[t][i] = 0.f;

        zgen(0, 0);                     // Z for first slab of this layer

        for (int ls = 0; ls < SPL; ++ls, ++s) {
            // Wait for W slab s (bulk complete_tx), then CTA-wide visibility.
            mbar_wait(sb + OFF_MB + (s % 3) * 8, (s / 3) & 1);
            __syncthreads();            // W(s)+Z(ls) ready; slot (s+2)%3 consumed

            // Prefetch W slab s+2 with a single bulk copy (streams under MMAs).
            if (tid == 0 && s + 2 < NSLAB) {
                const int pf = s + 2, slot = pf % 3;
                mbar_expect_tx(sb + OFF_MB + slot * 8, WSLAB);
                bulk_cp(sb + OFF_W + slot * WSLAB, g_wpack + (size_t)pf * WSLAB,
                        WSLAB, sb + OFF_MB + slot * 8);
            }
            // Z for the next slab (other slot; its consumers already synced past).
            if (ls + 1 < SPL) zgen(ls + 1, (ls + 1) & 1);

            const uint32_t wb = sb + OFF_W + (s % 3) * WSLAB;
            const uint32_t zb = sb + OFF_Z + (ls & 1) * ZSLAB;

            // This warp-group's half of K: k-steps kg2, kg2+1.
            #pragma unroll
            for (int kx = 0; kx < 2; ++kx) {
                const int kk = kg2 + kx;
                uint32_t ah[4], al[4], bh[8], bl[8];
                ldsm4(ah[0], ah[1], ah[2], ah[3], wb + SW128(aoff + kk*32));
                ldsm4(al[0], al[1], al[2], al[3], wb + 16384 + SW128(aoff + kk*32));
                ldsm4(bh[0], bh[1], bh[2], bh[3], zb + SW128(boff + kk*32));
                ldsm4(bh[4], bh[5], bh[6], bh[7], zb + SW128(boff + 2048 + kk*32));
                ldsm4(bl[0], bl[1], bl[2], bl[3], zb + 4096 + SW128(boff + kk*32));
                ldsm4(bl[4], bl[5], bl[6], bl[7], zb + 4096 + SW128(boff + 2048 + kk*32));
                #pragma unroll
                for (int t = 0; t < 4; ++t) {
                    mma_bf16(acc[t], ah, bh[2*t], bh[2*t+1]);   // hi*hi
                    mma_bf16(acc[t], al, bh[2*t], bh[2*t+1]);   // lo*hi
                    mma_bf16(acc[t], ah, bl[2*t], bl[2*t+1]);   // hi*lo
                }
            }
        }

        // ---- layer epilogue: combine the two k-group partials, relu/store ----
        __syncthreads();                        // all MMAs done; Z area reusable
        float* red = (float*)(sm + OFF_Z);      // 16KB scratch
        if (wid >= 8) {
            float* p = red + ((size_t)((wid - 8)*32 + lid))*16;
            #pragma unroll
            for (int t = 0; t < 4; ++t)
                #pragma unroll
                for (int i = 0; i < 4; ++i) p[t*4 + i] = acc[t][i];
        }
        __syncthreads();
        if (wid < 8) {
            float* p = red + ((size_t)(wid*32 + lid))*16;
            #pragma unroll
            for (int t = 0; t < 4; ++t)
                #pragma unroll
                for (int i = 0; i < 4; ++i) acc[t][i] += p[t*4 + i];

            // d-frag: c0:(q=16w+l/4, n=2(l%4)) c1:n+1 c2:q+8 c3:q+8,n+1 ; n += 8t
            const int qb = 16*w7 + (lid >> 2);
            const int nb = 2 * (lid & 3);
            if (layer < NLAYER - 1) {
                #pragma unroll
                for (int t = 0; t < 4; ++t) {
                    const int n = 8*t + nb;
                    hs[(n  )*HP + qb    ] = fmaxf(acc[t][0], 0.f);
                    hs[(n+1)*HP + qb    ] = fmaxf(acc[t][1], 0.f);
                    hs[(n  )*HP + qb + 8] = fmaxf(acc[t][2], 0.f);
                    hs[(n+1)*HP + qb + 8] = fmaxf(acc[t][3], 0.f);
                }
            } else {
                #pragma unroll
                for (int t = 0; t < 4; ++t) {
                    const int n = 8*t + nb;
                    gout[(size_t)(n0 + n    )*HDIM + qb    ] = acc[t][0];
                    gout[(size_t)(n0 + n + 1)*HDIM + qb    ] = acc[t][1];
                    gout[(size_t)(n0 + n    )*HDIM + qb + 8] = acc[t][2];
                    gout[(size_t)(n0 + n + 1)*HDIM + qb + 8] = acc[t][3];
                }
            }
        }
        __syncthreads();                // hs/scratch settled before next layer's zgen
    }
}

extern "C" void kernel_launch(void* const* d_in, const int* in_sizes, int n_in,
                              void* d_out, int out_size)
{
    const float *int_x = nullptr, *x = nullptr, *W = nullptr, *b = nullptr;
    for (int i = 0; i < n_in; ++i) {
        const int sz = in_sizes[i];
        if      (sz == NSAMP*IDIM)          int_x = (const float*)d_in[i];
        else if (sz == NSAMP*HDIM)          x     = (const float*)d_in[i];
        else if (sz == NLAYER*LSTRIDE*IDIM) W     = (const float*)d_in[i];
        else if (sz == NLAYER*LSTRIDE)      b     = (const float*)d_in[i];
    }

    prep_kernel<<<NSLAB, 256>>>(W, b);

    cudaFuncSetAttribute(inet_mma_kernel, cudaFuncAttributeMaxDynamicSharedMemorySize,
                         SMEM_ALLOC);
    inet_mma_kernel<<<NSAMP/NB, THREADS, SMEM_ALLOC>>>(int_x, x, (float*)d_out);
}

// round 12
// speedup vs baseline: 2.9044x; 1.1078x over previous
#include <cuda_runtime.h>
#include <cuda_bf16.h>
#include <cstdint>
#include <cstddef>

// ---------------- problem constants ----------------
#define NSAMP   4096
#define IDIM    512
#define HDIM    128
#define LSTRIDE (HDIM + HDIM*HDIM)       // 16512 rows of W per layer
#define NLAYER  3

// ---------------- tiling ----------------
#define NB      32                        // samples per CTA (GEMM N)
#define CHUNKS  129                       // 128 weight chunks + 1 x-chunk
#define SPC     8                         // 64-k slabs per chunk (K=512)
#define PSEUDO  3                         // bias-fold pseudo slabs (K=192, zero-padded)
#define SPL     (CHUNKS*SPC + PSEUDO)     // 1035 slabs per layer
#define NSLAB   (NLAYER*SPL)              // 3105 slabs total

#define WSLAB   32768                     // [128 x 64] bf16, hi(16K) + lo(16K), SW128
#define ZSLAB   8192                      // [32 x 64]  bf16, hi(4K)  + lo(4K),  SW128

#define XP      520                       // xs pitch (floats)
#define HP      132                       // hs pitch (floats)

#define OFF_W   0                         // 3 * 32768
#define OFF_Z   (3*WSLAB)                 // 2 * 8192 (also layer-end 16KB scratch grid)
#define OFF_X   (OFF_Z + 2*ZSLAB)
#define OFF_H   (OFF_X + NB*XP*4)
#define OFF_MB  (OFF_H + NB*HP*4)         // 3 mbarriers (8B each)
#define SMEM_ALLOC (OFF_MB + 64 + 1024)

#define THREADS 512                       // 16 warps: 4 q-blocks x 4 k-steps

#define SW128(x) ((x) ^ (((x) >> 3) & 0x70))

// ---------------- ptx helpers ----------------
__device__ __forceinline__ uint32_t smem_u32(const void* p) {
    uint32_t a;
    asm("{ .reg .u64 t; cvta.to.shared.u64 t, %1; cvt.u32.u64 %0, t; }" : "=r"(a) : "l"(p));
    return a;
}
__device__ __forceinline__ void cp16(uint32_t s, const void* g) {
    asm volatile("cp.async.cg.shared.global [%0], [%1], 16;" :: "r"(s), "l"(g));
}
#define CP_COMMIT() asm volatile("cp.async.commit_group;" ::: "memory")
#define CP_WAIT0()  asm volatile("cp.async.wait_group 0;" ::: "memory")

// Bulk async copy (single UBLKCP; completion via mbarrier complete_tx).
__device__ __forceinline__ void bulk_cp(uint32_t dst, const void* src,
                                        uint32_t bytes, uint32_t mbar) {
    asm volatile(
        "cp.async.bulk.shared::cta.global.mbarrier::complete_tx::bytes [%0], [%1], %2, [%3];"
        :: "r"(dst), "l"(src), "r"(bytes), "r"(mbar) : "memory");
}
__device__ __forceinline__ void mbar_init(uint32_t a, uint32_t cnt) {
    asm volatile("mbarrier.init.shared.b64 [%0], %1;" :: "r"(a), "r"(cnt) : "memory");
}
__device__ __forceinline__ void mbar_expect_tx(uint32_t a, uint32_t bytes) {
    asm volatile("mbarrier.arrive.expect_tx.shared.b64 _, [%0], %1;"
                 :: "r"(a), "r"(bytes) : "memory");
}
__device__ __forceinline__ void mbar_wait(uint32_t a, uint32_t parity) {
    uint32_t done;
    asm volatile(
        "{\n\t.reg .pred p;\n\t"
        "mbarrier.try_wait.parity.acquire.cta.shared::cta.b64 p, [%1], %2;\n\t"
        "selp.b32 %0, 1, 0, p;\n\t}" : "=r"(done) : "r"(a), "r"(parity) : "memory");
    if (!done) {
        asm volatile(
            "{\n\t.reg .pred P1;\n\t"
            "W_%=:\n\t"
            "mbarrier.try_wait.parity.acquire.cta.shared::cta.b64 P1, [%0], %1, 0x989680;\n\t"
            "@P1 bra.uni D_%=;\n\t"
            "bra.uni W_%=;\n\t"
            "D_%=:\n\t}" :: "r"(a), "r"(parity) : "memory");
    }
}

__device__ __forceinline__ void ldsm4(uint32_t& r0, uint32_t& r1, uint32_t& r2,
                                      uint32_t& r3, uint32_t addr) {
    asm volatile("ldmatrix.sync.aligned.m8n8.x4.shared.b16 {%0,%1,%2,%3}, [%4];"
                 : "=r"(r0), "=r"(r1), "=r"(r2), "=r"(r3) : "r"(addr));
}
__device__ __forceinline__ void mma_bf16(float* d, const uint32_t* a,
                                         uint32_t b0, uint32_t b1) {
    asm volatile(
        "mma.sync.aligned.m16n8k16.row.col.f32.bf16.bf16.f32 "
        "{%0,%1,%2,%3}, {%4,%5,%6,%7}, {%8,%9}, {%0,%1,%2,%3};"
        : "+f"(d[0]), "+f"(d[1]), "+f"(d[2]), "+f"(d[3])
        : "r"(a[0]), "r"(a[1]), "r"(a[2]), "r"(a[3]), "r"(b0), "r"(b1));
}
__device__ __forceinline__ void split2(float v0, float v1, unsigned& hi, unsigned& lo) {
    __nv_bfloat16 h0 = __float2bfloat16(v0), h1 = __float2bfloat16(v1);
    float r0 = v0 - __bfloat162float(h0);
    float r1 = v1 - __bfloat162float(h1);
    __nv_bfloat16 l0 = __float2bfloat16(r0), l1 = __float2bfloat16(r1);
    hi = (unsigned)__bfloat16_as_ushort(h0) | ((unsigned)__bfloat16_as_ushort(h1) << 16);
    lo = (unsigned)__bfloat16_as_ushort(l0) | ((unsigned)__bfloat16_as_ushort(l1) << 16);
}

// W pack: per-slab 32KB images (hi 16KB + lo 16KB), pre-swizzled, in stream order.
__device__ __align__(128) unsigned char g_wpack[(size_t)NSLAB * WSLAB];

// ---------------- prep: split W/b to bf16 hi/lo slab images ----------------
__global__ void prep_kernel(const float* __restrict__ W, const float* __restrict__ b) {
    const int s    = blockIdx.x;
    const int l    = s / SPL;
    const int sl   = s - l * SPL;
    const int base = l * LSTRIDE;
    unsigned char* dst = g_wpack + (size_t)s * WSLAB;

    for (int task = threadIdx.x; task < 1024; task += blockDim.x) {
        const int r = task >> 3, kb = task & 7;         // row 0..127, 8-elem k block
        float v[8];
        if (sl < CHUNKS * SPC) {
            const int c = sl >> 3, j = sl & 7;
            const int row = base + (c < HDIM ? HDIM + c * HDIM + r : r);
            const float* src = W + (size_t)row * IDIM + j * 64 + kb * 8;
            #pragma unroll
            for (int e = 0; e < 8; ++e) v[e] = src[e];
        } else {                                        // bias-fold pseudo slab
            const int j = sl - CHUNKS * SPC;
            #pragma unroll
            for (int e = 0; e < 8; ++e) {
                const int kg = j * 64 + kb * 8 + e;
                v[e] = (kg < HDIM) ? b[base + HDIM + kg * HDIM + r]
                                   : (kg == HDIM ? b[base + r] : 0.f);
            }
        }
        unsigned hi[4], lo[4];
        #pragma unroll
        for (int e = 0; e < 4; ++e) split2(v[2*e], v[2*e+1], hi[e], lo[e]);
        const unsigned off = SW128(r * 128 + kb * 16);
        *(uint4*)(dst + off)         = make_uint4(hi[0], hi[1], hi[2], hi[3]);
        *(uint4*)(dst + 16384 + off) = make_uint4(lo[0], lo[1], lo[2], lo[3]);
    }
}

// ---------------- main fused kernel ----------------
__global__ void __launch_bounds__(THREADS, 1)
inet_mma_kernel(const float* __restrict__ gx_int, const float* __restrict__ gx,
                float* __restrict__ gout)
{
    extern __shared__ __align__(16) unsigned char smraw[];
    const uint32_t sb0 = smem_u32(smraw);
    const uint32_t sb  = (sb0 + 1023) & ~1023u;        // 1024-align for SW128
    unsigned char* sm  = smraw + (sb - sb0);
    float* xs = (float*)(sm + OFF_X);
    float* hs = (float*)(sm + OFF_H);

    const int tid = threadIdx.x;
    const int wid = tid >> 5, lid = tid & 31;
    const int qb2 = wid >> 2;               // q-block: rows 32*qb2 .. +32
    const int kg  = wid & 3;                // this warp's k-step (16 k)
    const int n0  = blockIdx.x * NB;

    // Per-lane ldmatrix offset bases (bytes, pre-swizzle). Includes kg k-offset.
    const int g  = lid >> 3, lr = lid & 7;
    const int aoff = (32*qb2 + (g & 1)*8 + lr) * 128 + (g >> 1) * 16 + kg * 32;
    const int boff = ((g >> 1)*8 + lr) * 128 + (g & 1) * 16 + kg * 32;

    // mbarriers for the 3-slot W ring.
    if (tid == 0)
        for (int k = 0; k < 3; ++k) mbar_init(sb + OFF_MB + k * 8, 1);

    // Stage int_x tile (fp32) and initial h = x.
    for (int i = tid; i < NB * (IDIM/4); i += THREADS) {
        int n = i >> 7, k4 = i & 127;
        cp16(sb + OFF_X + (n*XP + k4*4)*4, gx_int + (size_t)(n0+n)*IDIM + k4*4);
    }
    for (int i = tid; i < NB * (HDIM/4); i += THREADS) {
        int n = i >> 5, q4 = i & 31;
        cp16(sb + OFF_H + (n*HP + q4*4)*4, gx + (size_t)(n0+n)*HDIM + q4*4);
    }
    CP_COMMIT(); CP_WAIT0();
    __syncthreads();                        // also orders mbar_init before use

    // Prologue: W slabs 0,1 -> ring slots 0,1 via single bulk copies.
    if (tid == 0) {
        #pragma unroll
        for (int p = 0; p < 2; ++p) {
            mbar_expect_tx(sb + OFF_MB + p * 8, WSLAB);
            bulk_cp(sb + OFF_W + p * WSLAB, g_wpack + (size_t)p * WSLAB,
                    WSLAB, sb + OFF_MB + p * 8);
        }
    }

    // Z generator: slab ls of current layer -> Z slot (hi/lo bf16, swizzled).
    const int zn = tid >> 4, zkb = tid & 15;            // row, 4-elem k block
    auto zgen = [&](int ls, int slot) {
        unsigned char* zp = sm + OFF_Z + slot * ZSLAB;
        const unsigned zoff = SW128(zn * 128 + zkb * 8);
        float v[4];
        if (ls < CHUNKS * SPC) {
            const int c = ls >> 3, j = ls & 7;
            const float m = (c < HDIM) ? hs[zn*HP + c] : 1.0f;
            const float4 xv = *(const float4*)&xs[zn*XP + j*64 + zkb*4];
            v[0] = m*xv.x; v[1] = m*xv.y; v[2] = m*xv.z; v[3] = m*xv.w;
        } else {
            const int j = ls - CHUNKS * SPC;
            #pragma unroll
            for (int e = 0; e < 4; ++e) {
                const int kgl = j*64 + zkb*4 + e;
                v[e] = (kgl < HDIM) ? hs[zn*HP + kgl] : (kgl == HDIM ? 1.f : 0.f);
            }
        }
        unsigned hi[2], lo[2];
        split2(v[0], v[1], hi[0], lo[0]);
        split2(v[2], v[3], hi[1], lo[1]);
        *(uint2*)(zp + zoff)        = make_uint2(hi[0], hi[1]);
        *(uint2*)(zp + 4096 + zoff) = make_uint2(lo[0], lo[1]);
    };

    int s = 0;
    for (int layer = 0; layer < NLAYER; ++layer) {
        float acc[2][4][4];                 // [q-subtile][n-tile][frag]
        #pragma unroll
        for (int st = 0; st < 2; ++st)
            #pragma unroll
            for (int t = 0; t < 4; ++t)
                #pragma unroll
                for (int i = 0; i < 4; ++i) acc[st][t][i] = 0.f;

        zgen(0, 0);                     // Z for first slab of this layer

        for (int ls = 0; ls < SPL; ++ls, ++s) {
            // Wait for W slab s (bulk complete_tx), then CTA-wide visibility.
            mbar_wait(sb + OFF_MB + (s % 3) * 8, (s / 3) & 1);
            __syncthreads();            // W(s)+Z(ls) ready; slot (s+2)%3 consumed

            // Prefetch W slab s+2 with a single bulk copy (streams under MMAs).
            if (tid == 0 && s + 2 < NSLAB) {
                const int pf = s + 2, slot = pf % 3;
                mbar_expect_tx(sb + OFF_MB + slot * 8, WSLAB);
                bulk_cp(sb + OFF_W + slot * WSLAB, g_wpack + (size_t)pf * WSLAB,
                        WSLAB, sb + OFF_MB + slot * 8);
            }
            // Z for the next slab (other slot; its consumers already synced past).
            if (ls + 1 < SPL) zgen(ls + 1, (ls + 1) & 1);

            const uint32_t wb = sb + OFF_W + (s % 3) * WSLAB;
            const uint32_t zb = sb + OFF_Z + (ls & 1) * ZSLAB;

            // This warp: 32 q-rows (2 subtiles) x 32 n x its 16-k step.
            uint32_t ah[2][4], al[2][4], bh[8], bl[8];
            #pragma unroll
            for (int st = 0; st < 2; ++st) {
                ldsm4(ah[st][0], ah[st][1], ah[st][2], ah[st][3],
                      wb + SW128(aoff + st*2048));
                ldsm4(al[st][0], al[st][1], al[st][2], al[st][3],
                      wb + 16384 + SW128(aoff + st*2048));
            }
            ldsm4(bh[0], bh[1], bh[2], bh[3], zb + SW128(boff));
            ldsm4(bh[4], bh[5], bh[6], bh[7], zb + SW128(boff + 2048));
            ldsm4(bl[0], bl[1], bl[2], bl[3], zb + 4096 + SW128(boff));
            ldsm4(bl[4], bl[5], bl[6], bl[7], zb + 4096 + SW128(boff + 2048));
            #pragma unroll
            for (int st = 0; st < 2; ++st)
                #pragma unroll
                for (int t = 0; t < 4; ++t) {
                    mma_bf16(acc[st][t], ah[st], bh[2*t], bh[2*t+1]);   // hi*hi
                    mma_bf16(acc[st][t], al[st], bh[2*t], bh[2*t+1]);   // lo*hi
                    mma_bf16(acc[st][t], ah[st], bl[2*t], bl[2*t+1]);   // hi*lo
                }
        }

        // ---- layer epilogue: 4-way k-group reduction via 16KB smem grid ----
        __syncthreads();                        // all MMAs done; Z area reusable
        float* grid = (float*)(sm + OFF_Z);     // [128][32]
        const int qrow = lid >> 2;
        const int nb   = 2 * (lid & 3);
        if (kg == 0) {
            #pragma unroll
            for (int st = 0; st < 2; ++st)
                #pragma unroll
                for (int t = 0; t < 4; ++t) {
                    const int q = 32*qb2 + 16*st + qrow, n = 8*t + nb;
                    *(float2*)&grid[(q    )*32 + n] = make_float2(acc[st][t][0], acc[st][t][1]);
                    *(float2*)&grid[(q + 8)*32 + n] = make_float2(acc[st][t][2], acc[st][t][3]);
                }
        }
        __syncthreads();
        #pragma unroll
        for (int p = 1; p < 4; ++p) {
            if (kg == p) {
                #pragma unroll
                for (int st = 0; st < 2; ++st)
                    #pragma unroll
                    for (int t = 0; t < 4; ++t) {
                        const int q = 32*qb2 + 16*st + qrow, n = 8*t + nb;
                        float2 v0 = *(float2*)&grid[(q    )*32 + n];
                        float2 v1 = *(float2*)&grid[(q + 8)*32 + n];
                        v0.x += acc[st][t][0]; v0.y += acc[st][t][1];
                        v1.x += acc[st][t][2]; v1.y += acc[st][t][3];
                        *(float2*)&grid[(q    )*32 + n] = v0;
                        *(float2*)&grid[(q + 8)*32 + n] = v1;
                    }
            }
            __syncthreads();
        }
        // read back: 8 cells per thread, relu -> hs or write gout
        {
            const int base = tid * 8;
            if (layer < NLAYER - 1) {
                #pragma unroll
                for (int e = 0; e < 8; ++e) {
                    const int q = (base + e) >> 5, n = (base + e) & 31;
                    hs[n*HP + q] = fmaxf(grid[base + e], 0.f);
                }
            } else {
                #pragma unroll
                for (int e = 0; e < 8; ++e) {
                    const int q = (base + e) >> 5, n = (base + e) & 31;
                    gout[(size_t)(n0 + n)*HDIM + q] = grid[base + e];
                }
            }
        }
        __syncthreads();                // grid/hs settled before next layer's zgen
    }
}

extern "C" void kernel_launch(void* const* d_in, const int* in_sizes, int n_in,
                              void* d_out, int out_size)
{
    const float *int_x = nullptr, *x = nullptr, *W = nullptr, *b = nullptr;
    for (int i = 0; i < n_in; ++i) {
        const int sz = in_sizes[i];
        if      (sz == NSAMP*IDIM)          int_x = (const float*)d_in[i];
        else if (sz == NSAMP*HDIM)          x     = (const float*)d_in[i];
        else if (sz == NLAYER*LSTRIDE*IDIM) W     = (const float*)d_in[i];
        else if (sz == NLAYER*LSTRIDE)      b     = (const float*)d_in[i];
    }

    prep_kernel<<<NSLAB, 256>>>(W, b);

    cudaFuncSetAttribute(inet_mma_kernel, cudaFuncAttributeMaxDynamicSharedMemorySize,
                         SMEM_ALLOC);
    inet_mma_kernel<<<NSAMP/NB, THREADS, SMEM_ALLOC>>>(int_x, x, (float*)d_out);
}

// round 13
// speedup vs baseline: 3.6716x; 1.2641x over previous
#include <cuda_runtime.h>
#include <cuda_bf16.h>
#include <cstdint>
#include <cstddef>

// ---------------- problem constants ----------------
#define NSAMP   4096
#define IDIM    512
#define HDIM    128
#define LSTRIDE (HDIM + HDIM*HDIM)       // 16512 rows of W per layer
#define NLAYER  3

// ---------------- tiling ----------------
#define NB      32                        // samples per CTA (GEMM N)
#define CHUNKS  129                       // 128 weight chunks + 1 x-chunk
#define SPC     8                         // 64-k slabs per chunk (K=512)
#define PSEUDO  4                         // bias-fold pseudo slabs (3 live + 1 zero pad)
#define SPL     (CHUNKS*SPC + PSEUDO)     // 1036 slabs per layer (even!)
#define NSLAB   (NLAYER*SPL)              // 3108 slabs total

#define WSLAB   32768                     // [128 x 64] bf16, hi(16K) + lo(16K), SW128
#define ZSLAB   8192                      // [32 x 64]  bf16, hi(4K)  + lo(4K),  SW128

#define HP      132                       // hs pitch (floats)

#define OFF_W   0                         // 4 * 32768 = 131072
#define OFF_Z   (4*WSLAB)                 // 4 * 8192  = 32768 (also epilogue grid)
#define OFF_H   (OFF_Z + 4*ZSLAB)         // 16896
#define OFF_MB  (OFF_H + NB*HP*4)         // 2 mbarriers (8B each)
#define SMEM_ALLOC (OFF_MB + 64 + 1024)

#define THREADS 512                       // 16 warps: 4 q-blocks x 4 k-steps

#define SW128(x) ((x) ^ (((x) >> 3) & 0x70))

// ---------------- ptx helpers ----------------
__device__ __forceinline__ uint32_t smem_u32(const void* p) {
    uint32_t a;
    asm("{ .reg .u64 t; cvta.to.shared.u64 t, %1; cvt.u32.u64 %0, t; }" : "=r"(a) : "l"(p));
    return a;
}
__device__ __forceinline__ void cp16(uint32_t s, const void* g) {
    asm volatile("cp.async.cg.shared.global [%0], [%1], 16;" :: "r"(s), "l"(g));
}
#define CP_COMMIT() asm volatile("cp.async.commit_group;" ::: "memory")
#define CP_WAIT0()  asm volatile("cp.async.wait_group 0;" ::: "memory")

// Bulk async copy (single UBLKCP; completion via mbarrier complete_tx).
__device__ __forceinline__ void bulk_cp(uint32_t dst, const void* src,
                                        uint32_t bytes, uint32_t mbar) {
    asm volatile(
        "cp.async.bulk.shared::cta.global.mbarrier::complete_tx::bytes [%0], [%1], %2, [%3];"
        :: "r"(dst), "l"(src), "r"(bytes), "r"(mbar) : "memory");
}
__device__ __forceinline__ void mbar_init(uint32_t a, uint32_t cnt) {
    asm volatile("mbarrier.init.shared.b64 [%0], %1;" :: "r"(a), "r"(cnt) : "memory");
}
__device__ __forceinline__ void mbar_expect_tx(uint32_t a, uint32_t bytes) {
    asm volatile("mbarrier.arrive.expect_tx.shared.b64 _, [%0], %1;"
                 :: "r"(a), "r"(bytes) : "memory");
}
__device__ __forceinline__ void mbar_wait(uint32_t a, uint32_t parity) {
    uint32_t done;
    asm volatile(
        "{\n\t.reg .pred p;\n\t"
        "mbarrier.try_wait.parity.acquire.cta.shared::cta.b64 p, [%1], %2;\n\t"
        "selp.b32 %0, 1, 0, p;\n\t}" : "=r"(done) : "r"(a), "r"(parity) : "memory");
    if (!done) {
        asm volatile(
            "{\n\t.reg .pred P1;\n\t"
            "W_%=:\n\t"
            "mbarrier.try_wait.parity.acquire.cta.shared::cta.b64 P1, [%0], %1, 0x989680;\n\t"
            "@P1 bra.uni D_%=;\n\t"
            "bra.uni W_%=;\n\t"
            "D_%=:\n\t}" :: "r"(a), "r"(parity) : "memory");
    }
}

__device__ __forceinline__ void ldsm4(uint32_t& r0, uint32_t& r1, uint32_t& r2,
                                      uint32_t& r3, uint32_t addr) {
    asm volatile("ldmatrix.sync.aligned.m8n8.x4.shared.b16 {%0,%1,%2,%3}, [%4];"
                 : "=r"(r0), "=r"(r1), "=r"(r2), "=r"(r3) : "r"(addr));
}
__device__ __forceinline__ void mma_bf16(float* d, const uint32_t* a,
                                         uint32_t b0, uint32_t b1) {
    asm volatile(
        "mma.sync.aligned.m16n8k16.row.col.f32.bf16.bf16.f32 "
        "{%0,%1,%2,%3}, {%4,%5,%6,%7}, {%8,%9}, {%0,%1,%2,%3};"
        : "+f"(d[0]), "+f"(d[1]), "+f"(d[2]), "+f"(d[3])
        : "r"(a[0]), "r"(a[1]), "r"(a[2]), "r"(a[3]), "r"(b0), "r"(b1));
}
__device__ __forceinline__ void split2(float v0, float v1, unsigned& hi, unsigned& lo) {
    __nv_bfloat16 h0 = __float2bfloat16(v0), h1 = __float2bfloat16(v1);
    float r0 = v0 - __bfloat162float(h0);
    float r1 = v1 - __bfloat162float(h1);
    __nv_bfloat16 l0 = __float2bfloat16(r0), l1 = __float2bfloat16(r1);
    hi = (unsigned)__bfloat16_as_ushort(h0) | ((unsigned)__bfloat16_as_ushort(h1) << 16);
    lo = (unsigned)__bfloat16_as_ushort(l0) | ((unsigned)__bfloat16_as_ushort(l1) << 16);
}

// W pack: per-slab 32KB images (hi 16KB + lo 16KB), pre-swizzled, in stream order.
__device__ __align__(128) unsigned char g_wpack[(size_t)NSLAB * WSLAB];

// ---------------- prep: split W/b to bf16 hi/lo slab images ----------------
__global__ void prep_kernel(const float* __restrict__ W, const float* __restrict__ b) {
    const int s    = blockIdx.x;
    const int l    = s / SPL;
    const int sl   = s - l * SPL;
    const int base = l * LSTRIDE;
    unsigned char* dst = g_wpack + (size_t)s * WSLAB;

    for (int task = threadIdx.x; task < 1024; task += blockDim.x) {
        const int r = task >> 3, kb = task & 7;         // row 0..127, 8-elem k block
        float v[8];
        if (sl < CHUNKS * SPC) {
            const int c = sl >> 3, j = sl & 7;
            const int row = base + (c < HDIM ? HDIM + c * HDIM + r : r);
            const float* src = W + (size_t)row * IDIM + j * 64 + kb * 8;
            #pragma unroll
            for (int e = 0; e < 8; ++e) v[e] = src[e];
        } else {                                        // bias-fold pseudo slab (j=3: zeros)
            const int j = sl - CHUNKS * SPC;
            #pragma unroll
            for (int e = 0; e < 8; ++e) {
                const int kg = j * 64 + kb * 8 + e;
                v[e] = (kg < HDIM) ? b[base + HDIM + kg * HDIM + r]
                                   : (kg == HDIM ? b[base + r] : 0.f);
            }
        }
        unsigned hi[4], lo[4];
        #pragma unroll
        for (int e = 0; e < 4; ++e) split2(v[2*e], v[2*e+1], hi[e], lo[e]);
        const unsigned off = SW128(r * 128 + kb * 16);
        *(uint4*)(dst + off)         = make_uint4(hi[0], hi[1], hi[2], hi[3]);
        *(uint4*)(dst + 16384 + off) = make_uint4(lo[0], lo[1], lo[2], lo[3]);
    }
}

// Z store: 4 fp32 -> bf16 hi/lo, swizzled, into slot slab&3.
__device__ __forceinline__ void zstore(unsigned char* sm, int slab, int zn, int zkb,
                                       float v0, float v1, float v2, float v3) {
    unsigned char* zp = sm + OFF_Z + (slab & 3) * ZSLAB;
    const unsigned zoff = SW128(zn * 128 + zkb * 8);
    unsigned hi0, lo0, hi1, lo1;
    split2(v0, v1, hi0, lo0);
    split2(v2, v3, hi1, lo1);
    *(uint2*)(zp + zoff)        = make_uint2(hi0, hi1);
    *(uint2*)(zp + 4096 + zoff) = make_uint2(lo0, lo1);
}

// Chunk zgen: slab (c, J); J must be a literal (xr register indexing).
#define ZGEN_CHUNK(cc, J, sslab) do { \
    const float m_ = ((cc) < HDIM) ? hs[zn*HP + (cc)] : 1.0f; \
    zstore(sm, (sslab), zn, zkb, m_*xr[J][0], m_*xr[J][1], m_*xr[J][2], m_*xr[J][3]); \
} while (0)

// Pseudo zgen: pseudo slab index J (0..3); z = h-fold columns (J=3 -> zeros).
#define ZGEN_PSEUDO(J, sslab) do { \
    float v_[4]; \
    _Pragma("unroll") \
    for (int e_ = 0; e_ < 4; ++e_) { \
        const int kgl_ = (J)*64 + zkb*4 + e_; \
        v_[e_] = (kgl_ < HDIM) ? hs[zn*HP + kgl_] : (kgl_ == HDIM ? 1.f : 0.f); \
    } \
    zstore(sm, (sslab), zn, zkb, v_[0], v_[1], v_[2], v_[3]); \
} while (0)

// ---------------- main fused kernel ----------------
__global__ void __launch_bounds__(THREADS, 1)
inet_mma_kernel(const float* __restrict__ gx_int, const float* __restrict__ gx,
                float* __restrict__ gout)
{
    extern __shared__ __align__(16) unsigned char smraw[];
    const uint32_t sb0 = smem_u32(smraw);
    const uint32_t sb  = (sb0 + 1023) & ~1023u;        // 1024-align for SW128
    unsigned char* sm  = smraw + (sb - sb0);
    float* hs = (float*)(sm + OFF_H);

    const int tid = threadIdx.x;
    const int wid = tid >> 5, lid = tid & 31;
    const int qb2 = wid >> 2;               // q-block: rows 32*qb2 .. +32
    const int kg  = wid & 3;                // this warp's k-step (16 k)
    const int n0  = blockIdx.x * NB;

    // Per-lane ldmatrix offset bases (bytes, pre-swizzle). Includes kg k-offset.
    const int g  = lid >> 3, lr = lid & 7;
    const int aoff = (32*qb2 + (g & 1)*8 + lr) * 128 + (g >> 1) * 16 + kg * 32;
    const int boff = ((g >> 1)*8 + lr) * 128 + (g & 1) * 16 + kg * 32;

    // zgen role: row zn, 4-elem k block zkb.
    const int zn = tid >> 4, zkb = tid & 15;

    // int_x held entirely in registers: xr[j][e] = x[zn, j*64 + zkb*4 + e].
    float xr[8][4];
    #pragma unroll
    for (int j = 0; j < 8; ++j) {
        const float4 t = *(const float4*)&gx_int[(size_t)(n0+zn)*IDIM + j*64 + zkb*4];
        xr[j][0] = t.x; xr[j][1] = t.y; xr[j][2] = t.z; xr[j][3] = t.w;
    }

    // 2 mbarriers (one per pair-half of the 4-slot W ring).
    if (tid == 0) { mbar_init(sb + OFF_MB, 1); mbar_init(sb + OFF_MB + 8, 1); }

    // Stage initial h = x.
    for (int i = tid; i < NB * (HDIM/4); i += THREADS) {
        int n = i >> 5, q4 = i & 31;
        cp16(sb + OFF_H + (n*HP + q4*4)*4, gx + (size_t)(n0+n)*HDIM + q4*4);
    }
    CP_COMMIT(); CP_WAIT0();
    __syncthreads();                        // hs + mbar_init visible

    // Prologue: W pairs 0 (slabs 0,1) and 1 (slabs 2,3), one 64KB bulk each.
    if (tid == 0) {
        mbar_expect_tx(sb + OFF_MB, 2*WSLAB);
        bulk_cp(sb + OFF_W, g_wpack, 2*WSLAB, sb + OFF_MB);
        mbar_expect_tx(sb + OFF_MB + 8, 2*WSLAB);
        bulk_cp(sb + OFF_W + 2*WSLAB, g_wpack + (size_t)2*WSLAB, 2*WSLAB,
                sb + OFF_MB + 8);
    }

    // Pair begin: wait this pair's W, CTA barrier, prefetch pair u+1 into
    // pair u-1's (now provably free) slots.
    auto pair_begin = [&](int s) {
        mbar_wait(sb + OFF_MB + ((s >> 1) & 1) * 8, (s >> 2) & 1);
        __syncthreads();
        if (tid == 0 && s >= 2 && s + 2 < NSLAB) {
            const uint32_t mb = sb + OFF_MB + (((s + 2) >> 1) & 1) * 8;
            mbar_expect_tx(mb, 2*WSLAB);
            bulk_cp(sb + OFF_W + ((s + 2) & 3) * WSLAB,
                    g_wpack + (size_t)(s + 2) * WSLAB, 2*WSLAB, mb);
        }
    };

    int s = 0;
    for (int layer = 0; layer < NLAYER; ++layer) {
        float acc[2][4][4];                 // [q-subtile][n-tile][frag]
        #pragma unroll
        for (int st = 0; st < 2; ++st)
            #pragma unroll
            for (int t = 0; t < 4; ++t)
                #pragma unroll
                for (int i = 0; i < 4; ++i) acc[st][t][i] = 0.f;

        auto mma_slab = [&](int slab) {
            const uint32_t wb = sb + OFF_W + (slab & 3) * WSLAB;
            const uint32_t zb = sb + OFF_Z + (slab & 3) * ZSLAB;
            uint32_t ah[2][4], al[2][4], bh[8], bl[8];
            #pragma unroll
            for (int st = 0; st < 2; ++st) {
                ldsm4(ah[st][0], ah[st][1], ah[st][2], ah[st][3],
                      wb + SW128(aoff + st*2048));
                ldsm4(al[st][0], al[st][1], al[st][2], al[st][3],
                      wb + 16384 + SW128(aoff + st*2048));
            }
            ldsm4(bh[0], bh[1], bh[2], bh[3], zb + SW128(boff));
            ldsm4(bh[4], bh[5], bh[6], bh[7], zb + SW128(boff + 2048));
            ldsm4(bl[0], bl[1], bl[2], bl[3], zb + 4096 + SW128(boff));
            ldsm4(bl[4], bl[5], bl[6], bl[7], zb + 4096 + SW128(boff + 2048));
            #pragma unroll
            for (int st = 0; st < 2; ++st)
                #pragma unroll
                for (int t = 0; t < 4; ++t) {
                    mma_bf16(acc[st][t], ah[st], bh[2*t], bh[2*t+1]);   // hi*hi
                    mma_bf16(acc[st][t], al[st], bh[2*t], bh[2*t+1]);   // lo*hi
                    mma_bf16(acc[st][t], ah[st], bl[2*t], bl[2*t+1]);   // hi*lo
                }
        };

        if (layer == 0) { ZGEN_CHUNK(0, 0, 0); ZGEN_CHUNK(0, 1, 1); } // Z for pair 0

        for (int c = 0; c < CHUNKS; ++c) {
            #pragma unroll
            for (int p = 0; p < 4; ++p) {
                pair_begin(s);
                // zgen for the NEXT pair (its Z slots are the free half).
                if (p == 0)      { ZGEN_CHUNK(c, 2, s+2); ZGEN_CHUNK(c, 3, s+3); }
                else if (p == 1) { ZGEN_CHUNK(c, 4, s+2); ZGEN_CHUNK(c, 5, s+3); }
                else if (p == 2) { ZGEN_CHUNK(c, 6, s+2); ZGEN_CHUNK(c, 7, s+3); }
                else if (c < CHUNKS-1) { ZGEN_CHUNK(c+1, 0, s+2); ZGEN_CHUNK(c+1, 1, s+3); }
                else             { ZGEN_PSEUDO(0, s+2); ZGEN_PSEUDO(1, s+3); }
                mma_slab(s); mma_slab(s+1);
                s += 2;
            }
        }
        // pseudo pair A (slabs j=0,1): zgen pseudo pair B
        pair_begin(s);
        ZGEN_PSEUDO(2, s+2); ZGEN_PSEUDO(3, s+3);
        mma_slab(s); mma_slab(s+1); s += 2;
        // pseudo pair B (slabs j=2,3): no zgen (epilogue next)
        pair_begin(s);
        mma_slab(s); mma_slab(s+1); s += 2;

        // ---- layer epilogue: 4-way k-group reduction via 16KB smem grid ----
        __syncthreads();                        // all MMAs done; Z area reusable
        float* grid = (float*)(sm + OFF_Z);     // [128][32]
        const int qrow = lid >> 2;
        const int nb   = 2 * (lid & 3);
        if (kg == 0) {
            #pragma unroll
            for (int st = 0; st < 2; ++st)
                #pragma unroll
                for (int t = 0; t < 4; ++t) {
                    const int q = 32*qb2 + 16*st + qrow, n = 8*t + nb;
                    *(float2*)&grid[(q    )*32 + n] = make_float2(acc[st][t][0], acc[st][t][1]);
                    *(float2*)&grid[(q + 8)*32 + n] = make_float2(acc[st][t][2], acc[st][t][3]);
                }
        }
        __syncthreads();
        #pragma unroll
        for (int p = 1; p < 4; ++p) {
            if (kg == p) {
                #pragma unroll
                for (int st = 0; st < 2; ++st)
                    #pragma unroll
                    for (int t = 0; t < 4; ++t) {
                        const int q = 32*qb2 + 16*st + qrow, n = 8*t + nb;
                        float2 v0 = *(float2*)&grid[(q    )*32 + n];
                        float2 v1 = *(float2*)&grid[(q + 8)*32 + n];
                        v0.x += acc[st][t][0]; v0.y += acc[st][t][1];
                        v1.x += acc[st][t][2]; v1.y += acc[st][t][3];
                        *(float2*)&grid[(q    )*32 + n] = v0;
                        *(float2*)&grid[(q + 8)*32 + n] = v1;
                    }
            }
            __syncthreads();
        }
        // read back: 8 cells per thread, relu -> hs or write gout
        {
            const int base = tid * 8;
            if (layer < NLAYER - 1) {
                #pragma unroll
                for (int e = 0; e < 8; ++e) {
                    const int q = (base + e) >> 5, n = (base + e) & 31;
                    hs[n*HP + q] = fmaxf(grid[base + e], 0.f);
                }
            } else {
                #pragma unroll
                for (int e = 0; e < 8; ++e) {
                    const int q = (base + e) >> 5, n = (base + e) & 31;
                    gout[(size_t)(n0 + n)*HDIM + q] = grid[base + e];
                }
            }
        }
        __syncthreads();                        // hs/grid settled

        // Z for the first pair of the NEXT layer (new hs; overwrites grid area).
        if (layer < NLAYER - 1) { ZGEN_CHUNK(0, 0, s); ZGEN_CHUNK(0, 1, s+1); }
    }
}

extern "C" void kernel_launch(void* const* d_in, const int* in_sizes, int n_in,
                              void* d_out, int out_size)
{
    const float *int_x = nullptr, *x = nullptr, *W = nullptr, *b = nullptr;
    for (int i = 0; i < n_in; ++i) {
        const int sz = in_sizes[i];
        if      (sz == NSAMP*IDIM)          int_x = (const float*)d_in[i];
        else if (sz == NSAMP*HDIM)          x     = (const float*)d_in[i];
        else if (sz == NLAYER*LSTRIDE*IDIM) W     = (const float*)d_in[i];
        else if (sz == NLAYER*LSTRIDE)      b     = (const float*)d_in[i];
    }

    prep_kernel<<<NSLAB, 256>>>(W, b);

    cudaFuncSetAttribute(inet_mma_kernel, cudaFuncAttributeMaxDynamicSharedMemorySize,
                         SMEM_ALLOC);
    inet_mma_kernel<<<NSAMP/NB, THREADS, SMEM_ALLOC>>>(int_x, x, (float*)d_out);
}

// round 14
// speedup vs baseline: 5.1950x; 1.4149x over previous
#include <cuda_runtime.h>
#include <cuda_fp16.h>
#include <cstdint>
#include <cstddef>

// ---------------- problem constants ----------------
#define NSAMP   4096
#define IDIM    512
#define HDIM    128
#define LSTRIDE (HDIM + HDIM*HDIM)       // 16512 rows of W per layer
#define NLAYER  3

// ---------------- tiling ----------------
#define NB      32                        // samples per CTA (GEMM N)
#define CHUNKS  129                       // 128 weight chunks + 1 x-chunk
#define SPC     8                         // 64-k slabs per chunk (K=512)
#define PSEUDO  4                         // bias-fold pseudo slabs (3 live + 1 zero pad)
#define SPL     (CHUNKS*SPC + PSEUDO)     // 1036 slabs per layer (even)
#define NSLAB   (NLAYER*SPL)              // 3108 slabs total

#define WSLAB   32768                     // [128 x 64] fp16, hi(16K) + lo(16K), SW128
#define ZSLAB   4096                      // [32 x 64]  fp16 single image, SW128

#define HP      132                       // hs pitch (floats)

#define OFF_W   0                         // 4 * 32768 = 131072
#define OFF_Z   (4*WSLAB)                 // 4 * 4096 = 16384 (doubles as epilogue grid)
#define OFF_H   (OFF_Z + 4*ZSLAB)
#define OFF_MB  (OFF_H + NB*HP*4)         // 2 mbarriers (8B each)
#define SMEM_ALLOC (OFF_MB + 64 + 1024)

#define THREADS 512                       // 16 warps: 4 q-blocks x 4 k-steps

#define SW128(x) ((x) ^ (((x) >> 3) & 0x70))

// ---------------- ptx helpers ----------------
__device__ __forceinline__ uint32_t smem_u32(const void* p) {
    uint32_t a;
    asm("{ .reg .u64 t; cvta.to.shared.u64 t, %1; cvt.u32.u64 %0, t; }" : "=r"(a) : "l"(p));
    return a;
}
__device__ __forceinline__ void cp16(uint32_t s, const void* g) {
    asm volatile("cp.async.cg.shared.global [%0], [%1], 16;" :: "r"(s), "l"(g));
}
#define CP_COMMIT() asm volatile("cp.async.commit_group;" ::: "memory")
#define CP_WAIT0()  asm volatile("cp.async.wait_group 0;" ::: "memory")

// Bulk async copy (single UBLKCP; completion via mbarrier complete_tx).
__device__ __forceinline__ void bulk_cp(uint32_t dst, const void* src,
                                        uint32_t bytes, uint32_t mbar) {
    asm volatile(
        "cp.async.bulk.shared::cta.global.mbarrier::complete_tx::bytes [%0], [%1], %2, [%3];"
        :: "r"(dst), "l"(src), "r"(bytes), "r"(mbar) : "memory");
}
__device__ __forceinline__ void mbar_init(uint32_t a, uint32_t cnt) {
    asm volatile("mbarrier.init.shared.b64 [%0], %1;" :: "r"(a), "r"(cnt) : "memory");
}
__device__ __forceinline__ void mbar_expect_tx(uint32_t a, uint32_t bytes) {
    asm volatile("mbarrier.arrive.expect_tx.shared.b64 _, [%0], %1;"
                 :: "r"(a), "r"(bytes) : "memory");
}
__device__ __forceinline__ void mbar_wait(uint32_t a, uint32_t parity) {
    uint32_t done;
    asm volatile(
        "{\n\t.reg .pred p;\n\t"
        "mbarrier.try_wait.parity.acquire.cta.shared::cta.b64 p, [%1], %2;\n\t"
        "selp.b32 %0, 1, 0, p;\n\t}" : "=r"(done) : "r"(a), "r"(parity) : "memory");
    if (!done) {
        asm volatile(
            "{\n\t.reg .pred P1;\n\t"
            "W_%=:\n\t"
            "mbarrier.try_wait.parity.acquire.cta.shared::cta.b64 P1, [%0], %1, 0x989680;\n\t"
            "@P1 bra.uni D_%=;\n\t"
            "bra.uni W_%=;\n\t"
            "D_%=:\n\t}" :: "r"(a), "r"(parity) : "memory");
    }
}

__device__ __forceinline__ void ldsm4(uint32_t& r0, uint32_t& r1, uint32_t& r2,
                                      uint32_t& r3, uint32_t addr) {
    asm volatile("ldmatrix.sync.aligned.m8n8.x4.shared.b16 {%0,%1,%2,%3}, [%4];"
                 : "=r"(r0), "=r"(r1), "=r"(r2), "=r"(r3) : "r"(addr));
}
__device__ __forceinline__ void mma_fp16(float* d, const uint32_t* a,
                                         uint32_t b0, uint32_t b1) {
    asm volatile(
        "mma.sync.aligned.m16n8k16.row.col.f32.f16.f16.f32 "
        "{%0,%1,%2,%3}, {%4,%5,%6,%7}, {%8,%9}, {%0,%1,%2,%3};"
        : "+f"(d[0]), "+f"(d[1]), "+f"(d[2]), "+f"(d[3])
        : "r"(a[0]), "r"(a[1]), "r"(a[2]), "r"(a[3]), "r"(b0), "r"(b1));
}
// fp16 hi/lo split of two fp32 values (W prep).
__device__ __forceinline__ void splitf(float v0, float v1, unsigned& hi, unsigned& lo) {
    __half h0 = __float2half_rn(v0), h1 = __float2half_rn(v1);
    float r0 = v0 - __half2float(h0);
    float r1 = v1 - __half2float(h1);
    __half l0 = __float2half_rn(r0), l1 = __float2half_rn(r1);
    hi = (unsigned)__half_as_ushort(h0) | ((unsigned)__half_as_ushort(h1) << 16);
    lo = (unsigned)__half_as_ushort(l0) | ((unsigned)__half_as_ushort(l1) << 16);
}
__device__ __forceinline__ unsigned packh2(float v0, float v1) {
    __half2 h = __floats2half2_rn(v0, v1);
    return *reinterpret_cast<unsigned*>(&h);
}

// W pack: per-slab 32KB images (hi 16KB + lo 16KB), pre-swizzled, in stream order.
__device__ __align__(128) unsigned char g_wpack[(size_t)NSLAB * WSLAB];

// ---------------- prep: split W/b to fp16 hi/lo slab images ----------------
__global__ void prep_kernel(const float* __restrict__ W, const float* __restrict__ b) {
    const int s    = blockIdx.x;
    const int l    = s / SPL;
    const int sl   = s - l * SPL;
    const int base = l * LSTRIDE;
    unsigned char* dst = g_wpack + (size_t)s * WSLAB;

    for (int task = threadIdx.x; task < 1024; task += blockDim.x) {
        const int r = task >> 3, kb = task & 7;         // row 0..127, 8-elem k block
        float v[8];
        if (sl < CHUNKS * SPC) {
            const int c = sl >> 3, j = sl & 7;
            const int row = base + (c < HDIM ? HDIM + c * HDIM + r : r);
            const float* src = W + (size_t)row * IDIM + j * 64 + kb * 8;
            #pragma unroll
            for (int e = 0; e < 8; ++e) v[e] = src[e];
        } else {                                        // bias-fold pseudo slab (j=3: zeros)
            const int j = sl - CHUNKS * SPC;
            #pragma unroll
            for (int e = 0; e < 8; ++e) {
                const int kg = j * 64 + kb * 8 + e;
                v[e] = (kg < HDIM) ? b[base + HDIM + kg * HDIM + r]
                                   : (kg == HDIM ? b[base + r] : 0.f);
            }
        }
        unsigned hi[4], lo[4];
        #pragma unroll
        for (int e = 0; e < 4; ++e) splitf(v[2*e], v[2*e+1], hi[e], lo[e]);
        const unsigned off = SW128(r * 128 + kb * 16);
        *(uint4*)(dst + off)         = make_uint4(hi[0], hi[1], hi[2], hi[3]);
        *(uint4*)(dst + 16384 + off) = make_uint4(lo[0], lo[1], lo[2], lo[3]);
    }
}

// Z store: 4 fp32 -> 4 fp16 (single image), swizzled, into slot slab&3.
__device__ __forceinline__ void zstore(unsigned char* sm, int slab, int zn, int zkb,
                                       float v0, float v1, float v2, float v3) {
    unsigned char* zp = sm + OFF_Z + (slab & 3) * ZSLAB;
    const unsigned zoff = SW128(zn * 128 + zkb * 8);
    *(uint2*)(zp + zoff) = make_uint2(packh2(v0, v1), packh2(v2, v3));
}

// Chunk zgen: slab (c, J); J must be a literal (xr register indexing).
#define ZGEN_CHUNK(cc, J, sslab) do { \
    const float m_ = ((cc) < HDIM) ? hs[zn*HP + (cc)] : 1.0f; \
    zstore(sm, (sslab), zn, zkb, m_*xr[J][0], m_*xr[J][1], m_*xr[J][2], m_*xr[J][3]); \
} while (0)

// Pseudo zgen: pseudo slab index J (0..3); z = h-fold columns (J=3 -> zeros).
#define ZGEN_PSEUDO(J, sslab) do { \
    float v_[4]; \
    _Pragma("unroll") \
    for (int e_ = 0; e_ < 4; ++e_) { \
        const int kgl_ = (J)*64 + zkb*4 + e_; \
        v_[e_] = (kgl_ < HDIM) ? hs[zn*HP + kgl_] : (kgl_ == HDIM ? 1.f : 0.f); \
    } \
    zstore(sm, (sslab), zn, zkb, v_[0], v_[1], v_[2], v_[3]); \
} while (0)

// ---------------- main fused kernel ----------------
__global__ void __launch_bounds__(THREADS, 1)
inet_mma_kernel(const float* __restrict__ gx_int, const float* __restrict__ gx,
                float* __restrict__ gout)
{
    extern __shared__ __align__(16) unsigned char smraw[];
    const uint32_t sb0 = smem_u32(smraw);
    const uint32_t sb  = (sb0 + 1023) & ~1023u;        // 1024-align for SW128
    unsigned char* sm  = smraw + (sb - sb0);
    float* hs = (float*)(sm + OFF_H);

    const int tid = threadIdx.x;
    const int wid = tid >> 5, lid = tid & 31;
    const int qb2 = wid >> 2;               // q-block: rows 32*qb2 .. +32
    const int kg  = wid & 3;                // this warp's k-step (16 k)
    const int n0  = blockIdx.x * NB;

    // Per-lane ldmatrix offset bases (bytes, pre-swizzle). Includes kg k-offset.
    const int g  = lid >> 3, lr = lid & 7;
    const int aoff = (32*qb2 + (g & 1)*8 + lr) * 128 + (g >> 1) * 16 + kg * 32;
    const int boff = ((g >> 1)*8 + lr) * 128 + (g & 1) * 16 + kg * 32;

    // zgen role: row zn, 4-elem k block zkb.
    const int zn = tid >> 4, zkb = tid & 15;

    // int_x held entirely in registers: xr[j][e] = x[zn, j*64 + zkb*4 + e].
    float xr[8][4];
    #pragma unroll
    for (int j = 0; j < 8; ++j) {
        const float4 t = *(const float4*)&gx_int[(size_t)(n0+zn)*IDIM + j*64 + zkb*4];
        xr[j][0] = t.x; xr[j][1] = t.y; xr[j][2] = t.z; xr[j][3] = t.w;
    }

    // 2 mbarriers (one per pair-half of the 4-slot W ring).
    if (tid == 0) { mbar_init(sb + OFF_MB, 1); mbar_init(sb + OFF_MB + 8, 1); }

    // Stage initial h = x.
    for (int i = tid; i < NB * (HDIM/4); i += THREADS) {
        int n = i >> 5, q4 = i & 31;
        cp16(sb + OFF_H + (n*HP + q4*4)*4, gx + (size_t)(n0+n)*HDIM + q4*4);
    }
    CP_COMMIT(); CP_WAIT0();
    __syncthreads();                        // hs + mbar_init visible

    // Prologue: W pairs 0 (slabs 0,1) and 1 (slabs 2,3), one 64KB bulk each.
    if (tid == 0) {
        mbar_expect_tx(sb + OFF_MB, 2*WSLAB);
        bulk_cp(sb + OFF_W, g_wpack, 2*WSLAB, sb + OFF_MB);
        mbar_expect_tx(sb + OFF_MB + 8, 2*WSLAB);
        bulk_cp(sb + OFF_W + 2*WSLAB, g_wpack + (size_t)2*WSLAB, 2*WSLAB,
                sb + OFF_MB + 8);
    }

    // Pair begin: wait this pair's W, CTA barrier, prefetch pair u+1 into
    // pair u-1's (now provably free) slots.
    auto pair_begin = [&](int s) {
        mbar_wait(sb + OFF_MB + ((s >> 1) & 1) * 8, (s >> 2) & 1);
        __syncthreads();
        if (tid == 0 && s >= 2 && s + 2 < NSLAB) {
            const uint32_t mb = sb + OFF_MB + (((s + 2) >> 1) & 1) * 8;
            mbar_expect_tx(mb, 2*WSLAB);
            bulk_cp(sb + OFF_W + ((s + 2) & 3) * WSLAB,
                    g_wpack + (size_t)(s + 2) * WSLAB, 2*WSLAB, mb);
        }
    };

    int s = 0;
    for (int layer = 0; layer < NLAYER; ++layer) {
        float acc[2][4][4];                 // [q-subtile][n-tile][frag]
        #pragma unroll
        for (int st = 0; st < 2; ++st)
            #pragma unroll
            for (int t = 0; t < 4; ++t)
                #pragma unroll
                for (int i = 0; i < 4; ++i) acc[st][t][i] = 0.f;

        auto mma_slab = [&](int slab) {
            const uint32_t wb = sb + OFF_W + (slab & 3) * WSLAB;
            const uint32_t zb = sb + OFF_Z + (slab & 3) * ZSLAB;
            uint32_t ah[2][4], al[2][4], bh[8];
            #pragma unroll
            for (int st = 0; st < 2; ++st) {
                ldsm4(ah[st][0], ah[st][1], ah[st][2], ah[st][3],
                      wb + SW128(aoff + st*2048));
                ldsm4(al[st][0], al[st][1], al[st][2], al[st][3],
                      wb + 16384 + SW128(aoff + st*2048));
            }
            ldsm4(bh[0], bh[1], bh[2], bh[3], zb + SW128(boff));
            ldsm4(bh[4], bh[5], bh[6], bh[7], zb + SW128(boff + 2048));
            #pragma unroll
            for (int st = 0; st < 2; ++st)
                #pragma unroll
                for (int t = 0; t < 4; ++t) {
                    mma_fp16(acc[st][t], ah[st], bh[2*t], bh[2*t+1]);   // w_hi * z
                    mma_fp16(acc[st][t], al[st], bh[2*t], bh[2*t+1]);   // w_lo * z
                }
        };

        if (layer == 0) { ZGEN_CHUNK(0, 0, 0); ZGEN_CHUNK(0, 1, 1); } // Z for pair 0

        for (int c = 0; c < CHUNKS; ++c) {
            #pragma unroll
            for (int p = 0; p < 4; ++p) {
                pair_begin(s);
                // zgen for the NEXT pair (its Z slots are the free half).
                if (p == 0)      { ZGEN_CHUNK(c, 2, s+2); ZGEN_CHUNK(c, 3, s+3); }
                else if (p == 1) { ZGEN_CHUNK(c, 4, s+2); ZGEN_CHUNK(c, 5, s+3); }
                else if (p == 2) { ZGEN_CHUNK(c, 6, s+2); ZGEN_CHUNK(c, 7, s+3); }
                else if (c < CHUNKS-1) { ZGEN_CHUNK(c+1, 0, s+2); ZGEN_CHUNK(c+1, 1, s+3); }
                else             { ZGEN_PSEUDO(0, s+2); ZGEN_PSEUDO(1, s+3); }
                mma_slab(s); mma_slab(s+1);
                s += 2;
            }
        }
        // pseudo pair A (slabs j=0,1): zgen pseudo pair B
        pair_begin(s);
        ZGEN_PSEUDO(2, s+2); ZGEN_PSEUDO(3, s+3);
        mma_slab(s); mma_slab(s+1); s += 2;
        // pseudo pair B (slabs j=2,3): no zgen (epilogue next)
        pair_begin(s);
        mma_slab(s); mma_slab(s+1); s += 2;

        // ---- layer epilogue: 4-way k-group reduction via 16KB smem grid ----
        __syncthreads();                        // all MMAs done; Z area reusable
        float* grid = (float*)(sm + OFF_Z);     // [128][32]
        const int qrow = lid >> 2;
        const int nb   = 2 * (lid & 3);
        if (kg == 0) {
            #pragma unroll
            for (int st = 0; st < 2; ++st)
                #pragma unroll
                for (int t = 0; t < 4; ++t) {
                    const int q = 32*qb2 + 16*st + qrow, n = 8*t + nb;
                    *(float2*)&grid[(q    )*32 + n] = make_float2(acc[st][t][0], acc[st][t][1]);
                    *(float2*)&grid[(q + 8)*32 + n] = make_float2(acc[st][t][2], acc[st][t][3]);
                }
        }
        __syncthreads();
        #pragma unroll
        for (int p = 1; p < 4; ++p) {
            if (kg == p) {
                #pragma unroll
                for (int st = 0; st < 2; ++st)
                    #pragma unroll
                    for (int t = 0; t < 4; ++t) {
                        const int q = 32*qb2 + 16*st + qrow, n = 8*t + nb;
                        float2 v0 = *(float2*)&grid[(q    )*32 + n];
                        float2 v1 = *(float2*)&grid[(q + 8)*32 + n];
                        v0.x += acc[st][t][0]; v0.y += acc[st][t][1];
                        v1.x += acc[st][t][2]; v1.y += acc[st][t][3];
                        *(float2*)&grid[(q    )*32 + n] = v0;
                        *(float2*)&grid[(q + 8)*32 + n] = v1;
                    }
            }
            __syncthreads();
        }
        // read back: 8 cells per thread, relu -> hs or write gout
        {
            const int base = tid * 8;
            if (layer < NLAYER - 1) {
                #pragma unroll
                for (int e = 0; e < 8; ++e) {
                    const int q = (base + e) >> 5, n = (base + e) & 31;
                    hs[n*HP + q] = fmaxf(grid[base + e], 0.f);
                }
            } else {
                #pragma unroll
                for (int e = 0; e < 8; ++e) {
                    const int q = (base + e) >> 5, n = (base + e) & 31;
                    gout[(size_t)(n0 + n)*HDIM + q] = grid[base + e];
                }
            }
        }
        __syncthreads();                        // hs/grid settled

        // Z for the first pair of the NEXT layer (new hs; overwrites grid area).
        if (layer < NLAYER - 1) { ZGEN_CHUNK(0, 0, s); ZGEN_CHUNK(0, 1, s+1); }
    }
}

extern "C" void kernel_launch(void* const* d_in, const int* in_sizes, int n_in,
                              void* d_out, int out_size)
{
    const float *int_x = nullptr, *x = nullptr, *W = nullptr, *b = nullptr;
    for (int i = 0; i < n_in; ++i) {
        const int sz = in_sizes[i];
        if      (sz == NSAMP*IDIM)          int_x = (const float*)d_in[i];
        else if (sz == NSAMP*HDIM)          x     = (const float*)d_in[i];
        else if (sz == NLAYER*LSTRIDE*IDIM) W     = (const float*)d_in[i];
        else if (sz == NLAYER*LSTRIDE)      b     = (const float*)d_in[i];
    }

    prep_kernel<<<NSLAB, 256>>>(W, b);

    cudaFuncSetAttribute(inet_mma_kernel, cudaFuncAttributeMaxDynamicSharedMemorySize,
                         SMEM_ALLOC);
    inet_mma_kernel<<<NSAMP/NB, THREADS, SMEM_ALLOC>>>(int_x, x, (float*)d_out);
}

// round 15
// speedup vs baseline: 6.5636x; 1.2635x over previous
#include <cuda_runtime.h>
#include <cuda_fp16.h>
#include <cstdint>
#include <cstddef>

// ---------------- problem constants ----------------
#define NSAMP   4096
#define IDIM    512
#define HDIM    128
#define LSTRIDE (HDIM + HDIM*HDIM)       // 16512 rows of W per layer
#define NLAYER  3

// ---------------- tiling ----------------
#define NB      32                        // samples per CTA (GEMM N)
#define CHUNKS  129                       // 128 weight chunks + 1 x-chunk
#define SPC     8                         // 64-k slabs per chunk (K=512)
#define PSEUDO  4                         // bias-fold pseudo slabs (3 live + 1 zero pad)
#define SPL     (CHUNKS*SPC + PSEUDO)     // 1036 slabs per layer (even)
#define NSLAB   (NLAYER*SPL)              // 3108 slabs total

#define WSLAB   16384                     // [128 x 64] fp16 single image, SW128
#define ZSLAB   4096                      // [32 x 64]  fp16 single image, SW128

#define HP      132                       // hs pitch (floats)

#define OFF_W   0                         // 4 * 16384 = 65536
#define OFF_Z   (4*WSLAB)                 // 4 * 4096 = 16384 (doubles as epilogue grid)
#define OFF_H   (OFF_Z + 4*ZSLAB)
#define OFF_MB  (OFF_H + NB*HP*4)         // 2 mbarriers (8B each)
#define SMEM_ALLOC (OFF_MB + 64 + 1024)

#define THREADS 512                       // 16 warps: 4 q-blocks x 4 k-steps

#define SW128(x) ((x) ^ (((x) >> 3) & 0x70))

// ---------------- ptx helpers ----------------
__device__ __forceinline__ uint32_t smem_u32(const void* p) {
    uint32_t a;
    asm("{ .reg .u64 t; cvta.to.shared.u64 t, %1; cvt.u32.u64 %0, t; }" : "=r"(a) : "l"(p));
    return a;
}
__device__ __forceinline__ void cp16(uint32_t s, const void* g) {
    asm volatile("cp.async.cg.shared.global [%0], [%1], 16;" :: "r"(s), "l"(g));
}
#define CP_COMMIT() asm volatile("cp.async.commit_group;" ::: "memory")
#define CP_WAIT0()  asm volatile("cp.async.wait_group 0;" ::: "memory")

// Bulk async copy (single UBLKCP; completion via mbarrier complete_tx).
__device__ __forceinline__ void bulk_cp(uint32_t dst, const void* src,
                                        uint32_t bytes, uint32_t mbar) {
    asm volatile(
        "cp.async.bulk.shared::cta.global.mbarrier::complete_tx::bytes [%0], [%1], %2, [%3];"
        :: "r"(dst), "l"(src), "r"(bytes), "r"(mbar) : "memory");
}
__device__ __forceinline__ void mbar_init(uint32_t a, uint32_t cnt) {
    asm volatile("mbarrier.init.shared.b64 [%0], %1;" :: "r"(a), "r"(cnt) : "memory");
}
__device__ __forceinline__ void mbar_expect_tx(uint32_t a, uint32_t bytes) {
    asm volatile("mbarrier.arrive.expect_tx.shared.b64 _, [%0], %1;"
                 :: "r"(a), "r"(bytes) : "memory");
}
__device__ __forceinline__ void mbar_wait(uint32_t a, uint32_t parity) {
    uint32_t done;
    asm volatile(
        "{\n\t.reg .pred p;\n\t"
        "mbarrier.try_wait.parity.acquire.cta.shared::cta.b64 p, [%1], %2;\n\t"
        "selp.b32 %0, 1, 0, p;\n\t}" : "=r"(done) : "r"(a), "r"(parity) : "memory");
    if (!done) {
        asm volatile(
            "{\n\t.reg .pred P1;\n\t"
            "W_%=:\n\t"
            "mbarrier.try_wait.parity.acquire.cta.shared::cta.b64 P1, [%0], %1, 0x989680;\n\t"
            "@P1 bra.uni D_%=;\n\t"
            "bra.uni W_%=;\n\t"
            "D_%=:\n\t}" :: "r"(a), "r"(parity) : "memory");
    }
}

__device__ __forceinline__ void ldsm4(uint32_t& r0, uint32_t& r1, uint32_t& r2,
                                      uint32_t& r3, uint32_t addr) {
    asm volatile("ldmatrix.sync.aligned.m8n8.x4.shared.b16 {%0,%1,%2,%3}, [%4];"
                 : "=r"(r0), "=r"(r1), "=r"(r2), "=r"(r3) : "r"(addr));
}
__device__ __forceinline__ void mma_fp16(float* d, const uint32_t* a,
                                         uint32_t b0, uint32_t b1) {
    asm volatile(
        "mma.sync.aligned.m16n8k16.row.col.f32.f16.f16.f32 "
        "{%0,%1,%2,%3}, {%4,%5,%6,%7}, {%8,%9}, {%0,%1,%2,%3};"
        : "+f"(d[0]), "+f"(d[1]), "+f"(d[2]), "+f"(d[3])
        : "r"(a[0]), "r"(a[1]), "r"(a[2]), "r"(a[3]), "r"(b0), "r"(b1));
}
__device__ __forceinline__ unsigned packh2(float v0, float v1) {
    __half2 h = __floats2half2_rn(v0, v1);
    return *reinterpret_cast<unsigned*>(&h);
}

// W pack: per-slab 16KB single-fp16 images, pre-swizzled, in stream order.
__device__ __align__(128) unsigned char g_wpack[(size_t)NSLAB * WSLAB];

// ---------------- prep: W/b -> fp16 slab images ----------------
__global__ void prep_kernel(const float* __restrict__ W, const float* __restrict__ b) {
    const int s    = blockIdx.x;
    const int l    = s / SPL;
    const int sl   = s - l * SPL;
    const int base = l * LSTRIDE;
    unsigned char* dst = g_wpack + (size_t)s * WSLAB;

    for (int task = threadIdx.x; task < 1024; task += blockDim.x) {
        const int r = task >> 3, kb = task & 7;         // row 0..127, 8-elem k block
        float v[8];
        if (sl < CHUNKS * SPC) {
            const int c = sl >> 3, j = sl & 7;
            const int row = base + (c < HDIM ? HDIM + c * HDIM + r : r);
            const float* src = W + (size_t)row * IDIM + j * 64 + kb * 8;
            #pragma unroll
            for (int e = 0; e < 8; ++e) v[e] = src[e];
        } else {                                        // bias-fold pseudo slab (j=3: zeros)
            const int j = sl - CHUNKS * SPC;
            #pragma unroll
            for (int e = 0; e < 8; ++e) {
                const int kg = j * 64 + kb * 8 + e;
                v[e] = (kg < HDIM) ? b[base + HDIM + kg * HDIM + r]
                                   : (kg == HDIM ? b[base + r] : 0.f);
            }
        }
        const unsigned off = SW128(r * 128 + kb * 16);
        *(uint4*)(dst + off) = make_uint4(packh2(v[0], v[1]), packh2(v[2], v[3]),
                                          packh2(v[4], v[5]), packh2(v[6], v[7]));
    }
}

// Z store: 4 fp32 -> 4 fp16 (single image), swizzled, into slot slab&3.
__device__ __forceinline__ void zstore(unsigned char* sm, int slab, int zn, int zkb,
                                       float v0, float v1, float v2, float v3) {
    unsigned char* zp = sm + OFF_Z + (slab & 3) * ZSLAB;
    const unsigned zoff = SW128(zn * 128 + zkb * 8);
    *(uint2*)(zp + zoff) = make_uint2(packh2(v0, v1), packh2(v2, v3));
}

// Chunk zgen: slab (c, J); J must be a literal (xr register indexing).
#define ZGEN_CHUNK(cc, J, sslab) do { \
    const float m_ = ((cc) < HDIM) ? hs[zn*HP + (cc)] : 1.0f; \
    zstore(sm, (sslab), zn, zkb, m_*xr[J][0], m_*xr[J][1], m_*xr[J][2], m_*xr[J][3]); \
} while (0)

// Pseudo zgen: pseudo slab index J (0..3); z = h-fold columns (J=3 -> zeros).
#define ZGEN_PSEUDO(J, sslab) do { \
    float v_[4]; \
    _Pragma("unroll") \
    for (int e_ = 0; e_ < 4; ++e_) { \
        const int kgl_ = (J)*64 + zkb*4 + e_; \
        v_[e_] = (kgl_ < HDIM) ? hs[zn*HP + kgl_] : (kgl_ == HDIM ? 1.f : 0.f); \
    } \
    zstore(sm, (sslab), zn, zkb, v_[0], v_[1], v_[2], v_[3]); \
} while (0)

// ---------------- main fused kernel ----------------
__global__ void __launch_bounds__(THREADS, 1)
inet_mma_kernel(const float* __restrict__ gx_int, const float* __restrict__ gx,
                float* __restrict__ gout)
{
    extern __shared__ __align__(16) unsigned char smraw[];
    const uint32_t sb0 = smem_u32(smraw);
    const uint32_t sb  = (sb0 + 1023) & ~1023u;        // 1024-align for SW128
    unsigned char* sm  = smraw + (sb - sb0);
    float* hs = (float*)(sm + OFF_H);

    const int tid = threadIdx.x;
    const int wid = tid >> 5, lid = tid & 31;
    const int qb2 = wid >> 2;               // q-block: rows 32*qb2 .. +32
    const int kg  = wid & 3;                // this warp's k-step (16 k)
    const int n0  = blockIdx.x * NB;

    // Per-lane ldmatrix offset bases (bytes, pre-swizzle). Includes kg k-offset.
    const int g  = lid >> 3, lr = lid & 7;
    const int aoff = (32*qb2 + (g & 1)*8 + lr) * 128 + (g >> 1) * 16 + kg * 32;
    const int boff = ((g >> 1)*8 + lr) * 128 + (g & 1) * 16 + kg * 32;

    // zgen role: row zn, 4-elem k block zkb.
    const int zn = tid >> 4, zkb = tid & 15;

    // int_x held entirely in registers: xr[j][e] = x[zn, j*64 + zkb*4 + e].
    float xr[8][4];
    #pragma unroll
    for (int j = 0; j < 8; ++j) {
        const float4 t = *(const float4*)&gx_int[(size_t)(n0+zn)*IDIM + j*64 + zkb*4];
        xr[j][0] = t.x; xr[j][1] = t.y; xr[j][2] = t.z; xr[j][3] = t.w;
    }

    // 2 mbarriers (one per pair-half of the 4-slot W ring).
    if (tid == 0) { mbar_init(sb + OFF_MB, 1); mbar_init(sb + OFF_MB + 8, 1); }

    // Stage initial h = x.
    for (int i = tid; i < NB * (HDIM/4); i += THREADS) {
        int n = i >> 5, q4 = i & 31;
        cp16(sb + OFF_H + (n*HP + q4*4)*4, gx + (size_t)(n0+n)*HDIM + q4*4);
    }
    CP_COMMIT(); CP_WAIT0();
    __syncthreads();                        // hs + mbar_init visible

    // Prologue: W pairs 0 (slabs 0,1) and 1 (slabs 2,3), one 32KB bulk each.
    if (tid == 0) {
        mbar_expect_tx(sb + OFF_MB, 2*WSLAB);
        bulk_cp(sb + OFF_W, g_wpack, 2*WSLAB, sb + OFF_MB);
        mbar_expect_tx(sb + OFF_MB + 8, 2*WSLAB);
        bulk_cp(sb + OFF_W + 2*WSLAB, g_wpack + (size_t)2*WSLAB, 2*WSLAB,
                sb + OFF_MB + 8);
    }

    // Pair begin: wait this pair's W, CTA barrier, prefetch pair u+1 into
    // pair u-1's (now provably free) slots.
    auto pair_begin = [&](int s) {
        mbar_wait(sb + OFF_MB + ((s >> 1) & 1) * 8, (s >> 2) & 1);
        __syncthreads();
        if (tid == 0 && s >= 2 && s + 2 < NSLAB) {
            const uint32_t mb = sb + OFF_MB + (((s + 2) >> 1) & 1) * 8;
            mbar_expect_tx(mb, 2*WSLAB);
            bulk_cp(sb + OFF_W + ((s + 2) & 3) * WSLAB,
                    g_wpack + (size_t)(s + 2) * WSLAB, 2*WSLAB, mb);
        }
    };

    int s = 0;
    for (int layer = 0; layer < NLAYER; ++layer) {
        float acc[2][4][4];                 // [q-subtile][n-tile][frag]
        #pragma unroll
        for (int st = 0; st < 2; ++st)
            #pragma unroll
            for (int t = 0; t < 4; ++t)
                #pragma unroll
                for (int i = 0; i < 4; ++i) acc[st][t][i] = 0.f;

        auto mma_slab = [&](int slab) {
            const uint32_t wb = sb + OFF_W + (slab & 3) * WSLAB;
            const uint32_t zb = sb + OFF_Z + (slab & 3) * ZSLAB;
            uint32_t ah[2][4], bh[8];
            #pragma unroll
            for (int st = 0; st < 2; ++st)
                ldsm4(ah[st][0], ah[st][1], ah[st][2], ah[st][3],
                      wb + SW128(aoff + st*2048));
            ldsm4(bh[0], bh[1], bh[2], bh[3], zb + SW128(boff));
            ldsm4(bh[4], bh[5], bh[6], bh[7], zb + SW128(boff + 2048));
            #pragma unroll
            for (int st = 0; st < 2; ++st)
                #pragma unroll
                for (int t = 0; t < 4; ++t)
                    mma_fp16(acc[st][t], ah[st], bh[2*t], bh[2*t+1]);   // w * z
        };

        if (layer == 0) { ZGEN_CHUNK(0, 0, 0); ZGEN_CHUNK(0, 1, 1); } // Z for pair 0

        for (int c = 0; c < CHUNKS; ++c) {
            #pragma unroll
            for (int p = 0; p < 4; ++p) {
                pair_begin(s);
                // zgen for the NEXT pair (its Z slots are the free half).
                if (p == 0)      { ZGEN_CHUNK(c, 2, s+2); ZGEN_CHUNK(c, 3, s+3); }
                else if (p == 1) { ZGEN_CHUNK(c, 4, s+2); ZGEN_CHUNK(c, 5, s+3); }
                else if (p == 2) { ZGEN_CHUNK(c, 6, s+2); ZGEN_CHUNK(c, 7, s+3); }
                else if (c < CHUNKS-1) { ZGEN_CHUNK(c+1, 0, s+2); ZGEN_CHUNK(c+1, 1, s+3); }
                else             { ZGEN_PSEUDO(0, s+2); ZGEN_PSEUDO(1, s+3); }
                mma_slab(s); mma_slab(s+1);
                s += 2;
            }
        }
        // pseudo pair A (slabs j=0,1): zgen pseudo pair B
        pair_begin(s);
        ZGEN_PSEUDO(2, s+2); ZGEN_PSEUDO(3, s+3);
        mma_slab(s); mma_slab(s+1); s += 2;
        // pseudo pair B (slabs j=2,3): no zgen (epilogue next)
        pair_begin(s);
        mma_slab(s); mma_slab(s+1); s += 2;

        // ---- layer epilogue: 4-way k-group reduction via 16KB smem grid ----
        __syncthreads();                        // all MMAs done; Z area reusable
        float* grid = (float*)(sm + OFF_Z);     // [128][32]
        const int qrow = lid >> 2;
        const int nb   = 2 * (lid & 3);
        if (kg == 0) {
            #pragma unroll
            for (int st = 0; st < 2; ++st)
                #pragma unroll
                for (int t = 0; t < 4; ++t) {
                    const int q = 32*qb2 + 16*st + qrow, n = 8*t + nb;
                    *(float2*)&grid[(q    )*32 + n] = make_float2(acc[st][t][0], acc[st][t][1]);
                    *(float2*)&grid[(q + 8)*32 + n] = make_float2(acc[st][t][2], acc[st][t][3]);
                }
        }
        __syncthreads();
        #pragma unroll
        for (int p = 1; p < 4; ++p) {
            if (kg == p) {
                #pragma unroll
                for (int st = 0; st < 2; ++st)
                    #pragma unroll
                    for (int t = 0; t < 4; ++t) {
                        const int q = 32*qb2 + 16*st + qrow, n = 8*t + nb;
                        float2 v0 = *(float2*)&grid[(q    )*32 + n];
                        float2 v1 = *(float2*)&grid[(q + 8)*32 + n];
                        v0.x += acc[st][t][0]; v0.y += acc[st][t][1];
                        v1.x += acc[st][t][2]; v1.y += acc[st][t][3];
                        *(float2*)&grid[(q    )*32 + n] = v0;
                        *(float2*)&grid[(q + 8)*32 + n] = v1;
                    }
            }
            __syncthreads();
        }
        // read back: 8 cells per thread, relu -> hs or write gout
        {
            const int base = tid * 8;
            if (layer < NLAYER - 1) {
                #pragma unroll
                for (int e = 0; e < 8; ++e) {
                    const int q = (base + e) >> 5, n = (base + e) & 31;
                    hs[n*HP + q] = fmaxf(grid[base + e], 0.f);
                }
            } else {
                #pragma unroll
                for (int e = 0; e < 8; ++e) {
                    const int q = (base + e) >> 5, n = (base + e) & 31;
                    gout[(size_t)(n0 + n)*HDIM + q] = grid[base + e];
                }
            }
        }
        __syncthreads();                        // hs/grid settled

        // Z for the first pair of the NEXT layer (new hs; overwrites grid area).
        if (layer < NLAYER - 1) { ZGEN_CHUNK(0, 0, s); ZGEN_CHUNK(0, 1, s+1); }
    }
}

extern "C" void kernel_launch(void* const* d_in, const int* in_sizes, int n_in,
                              void* d_out, int out_size)
{
    const float *int_x = nullptr, *x = nullptr, *W = nullptr, *b = nullptr;
    for (int i = 0; i < n_in; ++i) {
        const int sz = in_sizes[i];
        if      (sz == NSAMP*IDIM)          int_x = (const float*)d_in[i];
        else if (sz == NSAMP*HDIM)          x     = (const float*)d_in[i];
        else if (sz == NLAYER*LSTRIDE*IDIM) W     = (const float*)d_in[i];
        else if (sz == NLAYER*LSTRIDE)      b     = (const float*)d_in[i];
    }

    prep_kernel<<<NSLAB, 256>>>(W, b);

    cudaFuncSetAttribute(inet_mma_kernel, cudaFuncAttributeMaxDynamicSharedMemorySize,
                         SMEM_ALLOC);
    inet_mma_kernel<<<NSAMP/NB, THREADS, SMEM_ALLOC>>>(int_x, x, (float*)d_out);
}